// round 14
// baseline (speedup 1.0000x reference)
#include <cuda_runtime.h>
#include <cuda_bf16.h>
#include <cstdint>

#define CB 4
#define CS 4096
#define CD 256
#define CT 256
#define CK 16
#define CIN 259

typedef long long ll;
typedef unsigned u32;
typedef __nv_bfloat16 bf16;

// ---------------- device scratch ----------------
__device__ bf16  g_hi[(size_t)CB * CS * CD];
__device__ float g_feat[CB * CS * CD];
__device__ float g_sq[CB * CS];
__device__ u32   g_gramk[(size_t)CB * CS * CS];        // 256MB packed keys
__device__ int   g_idx[CB * CS * CK];
__device__ bf16  g_h[CB * CS * CT];
__device__ float g_qg[CB * CS * CT];
__device__ bf16  g_kgh[CB * CS * CT];
__device__ bf16  g_vh[CB * CS * CT];
__device__ bf16  g_t1[(size_t)CB * CS * CK * CT];      // 128MB
__device__ bf16  g_attn[(size_t)CB * CS * CK * CT];    // 128MB
__device__ bf16  g_res[CB * CS * CT];
// transposed bf16 weights: 0=fc1,1=wv,2=g2,3=fc2,4=Wqg,5=Wkg
__device__ bf16  g_wT[6][CT * CT];

// ---------------- helpers ----------------
__device__ __forceinline__ uint32_t smem_u32(const void* p) {
    return (uint32_t)__cvta_generic_to_shared(p);
}
__device__ __forceinline__ void cp_async16(uint32_t s, const void* g) {
    asm volatile("cp.async.cg.shared.global [%0], [%1], 16;" :: "r"(s), "l"(g));
}
__device__ __forceinline__ void cp_commit() {
    asm volatile("cp.async.commit_group;" ::: "memory");
}
__device__ __forceinline__ void cp_wait1() {
    asm volatile("cp.async.wait_group 1;" ::: "memory");
}
__device__ __forceinline__ void cp_wait0() {
    asm volatile("cp.async.wait_group 0;" ::: "memory");
}
__device__ __forceinline__ void ldsm_x4(unsigned* r, uint32_t addr) {
    asm volatile("ldmatrix.sync.aligned.m8n8.x4.shared.b16 {%0,%1,%2,%3}, [%4];"
                 : "=r"(r[0]), "=r"(r[1]), "=r"(r[2]), "=r"(r[3]) : "r"(addr));
}
__device__ __forceinline__ void ldsm_x2(unsigned* r, uint32_t addr) {
    asm volatile("ldmatrix.sync.aligned.m8n8.x2.shared.b16 {%0,%1}, [%2];"
                 : "=r"(r[0]), "=r"(r[1]) : "r"(addr));
}
#define MMA_BF16(acc, ar, br) \
    asm volatile( \
        "mma.sync.aligned.m16n8k16.row.col.f32.bf16.bf16.f32 " \
        "{%0,%1,%2,%3}, {%4,%5,%6,%7}, {%8,%9}, {%0,%1,%2,%3};" \
        : "+f"((acc)[0]), "+f"((acc)[1]), "+f"((acc)[2]), "+f"((acc)[3]) \
        : "r"((ar)[0]), "r"((ar)[1]), "r"((ar)[2]), "r"((ar)[3]), \
          "r"((br)[0]), "r"((br)[1]))

__device__ __forceinline__ u32 key_xform(float sc) {
    u32 u = __float_as_uint(sc);
    return (u & 0x80000000u) ? ~u : (u | 0x80000000u);
}

// ---------------- pipelined bf16 HMMA GEMM with ldmatrix (3-stage) ----------------
static constexpr int ST_ROWB = 80;
static constexpr int ST_HALF = 128 * ST_ROWB;
static constexpr int ST_BYTES = 2 * ST_HALF;
static constexpr int SOFF_STG = 1024;
static constexpr int SMEM_MMA = SOFF_STG + 3 * ST_BYTES;

template <int OUT_BF16, bool BIAS, bool ADD_RES>
__global__ __launch_bounds__(256, 2)
void mma_gemm(const bf16* __restrict__ A, const bf16* __restrict__ B,
              const float* __restrict__ bias, const float* __restrict__ Rres,
              float* __restrict__ Cf, bf16* __restrict__ Ch,
              int N, int Kd, int lda, ll sA, ll sB, ll sC) {
    extern __shared__ char smem[];
    const int tid = threadIdx.x;
    const int warp = tid >> 5, lane = tid & 31;
    const int wm = warp >> 2, wn = warp & 3;
    const int g = lane >> 2, tc = lane & 3;
    const uint32_t sbase = smem_u32(smem);
    const ll z = blockIdx.z;
    const int bm = blockIdx.y * 128, bn = blockIdx.x * 128;
    const bf16* Ag = A + z * sA + (ll)bm * lda;
    const bf16* Bg = B + z * sB + (ll)bn * Kd;

    float* sbias = (float*)smem;
    if (BIAS && tid < 128) sbias[tid] = bias[bn + tid];

    float acc[4][4][4];
    #pragma unroll
    for (int i = 0; i < 4; i++)
        #pragma unroll
        for (int j = 0; j < 4; j++)
            #pragma unroll
            for (int c = 0; c < 4; c++) acc[i][j][c] = 0.f;

    const int nch = Kd >> 5;
    const int lr = tid >> 2;
    const int lc = (tid & 3) << 3;

    const int lrow = lane & 7, lm = lane >> 3;
    uint32_t aoff[4], boff[4];
    #pragma unroll
    for (int mt = 0; mt < 4; mt++)
        aoff[mt] = (uint32_t)((wm * 64 + mt * 16 + (lm & 1) * 8 + lrow) * ST_ROWB
                              + (lm >> 1) * 16);
    #pragma unroll
    for (int nt = 0; nt < 4; nt++)
        boff[nt] = (uint32_t)((wn * 32 + nt * 8 + lrow) * ST_ROWB + (lm & 1) * 16);

    auto load_stage = [&](int i, int s) {
        if (i < nch) {
            const int k0 = i << 5;
            uint32_t sa = sbase + SOFF_STG + s * ST_BYTES;
            uint32_t sb = sa + ST_HALF;
            #pragma unroll
            for (int j = 0; j < 2; j++) {
                int r = lr + j * 64;
                cp_async16(sa + r * ST_ROWB + lc * 2, Ag + (ll)r * lda + k0 + lc);
                cp_async16(sb + r * ST_ROWB + lc * 2, Bg + (ll)r * Kd + k0 + lc);
            }
        }
        cp_commit();
    };

    load_stage(0, 0);
    load_stage(1, 1);

    for (int i = 0; i < nch; i++) {
        cp_wait1();
        __syncthreads();
        load_stage(i + 2, (i + 2) % 3);

        const uint32_t stg = sbase + SOFF_STG + (i % 3) * ST_BYTES;
        #pragma unroll
        for (int ks = 0; ks < 2; ks++) {
            unsigned a_r[4][4], b_r[4][2];
            #pragma unroll
            for (int mt = 0; mt < 4; mt++)
                ldsm_x4(a_r[mt], stg + aoff[mt] + ks * 32);
            #pragma unroll
            for (int nt = 0; nt < 4; nt++)
                ldsm_x2(b_r[nt], stg + ST_HALF + boff[nt] + ks * 32);
            #pragma unroll
            for (int mt = 0; mt < 4; mt++)
                #pragma unroll
                for (int nt = 0; nt < 4; nt++)
                    MMA_BF16(acc[mt][nt], a_r[mt], b_r[nt]);
        }
    }

    #pragma unroll
    for (int mt = 0; mt < 4; mt++) {
        int r0 = bm + wm * 64 + mt * 16 + g;
        #pragma unroll
        for (int nt = 0; nt < 4; nt++) {
            int lcol = wn * 32 + nt * 8 + tc * 2;
            int c0 = bn + lcol;
            #pragma unroll
            for (int h = 0; h < 2; h++) {
                int rr = r0 + h * 8;
                float v0 = acc[mt][nt][h * 2 + 0];
                float v1 = acc[mt][nt][h * 2 + 1];
                if (BIAS) { v0 += sbias[lcol]; v1 += sbias[lcol + 1]; }
                if (ADD_RES) {
                    v0 += Rres[(ll)rr * N + c0];
                    v1 += Rres[(ll)rr * N + c0 + 1];
                }
                if (OUT_BF16) {
                    __nv_bfloat162 pk;
                    pk.x = __float2bfloat16(v0);
                    pk.y = __float2bfloat16(v1);
                    *(__nv_bfloat162*)(Ch + z * sC + (ll)rr * N + c0) = pk;
                } else {
                    *(float2*)(Cf + z * sC + (ll)rr * N + c0) = make_float2(v0, v1);
                }
            }
        }
    }
}

// ---------------- symmetric Gram -> packed u32 keys (upper-triangle tiles) ----------------
static constexpr int GS_SOFF = 2048;
static constexpr int GS_TP = 132;                             // u32 pitch (528B)
static constexpr int GS_SMEM = GS_SOFF + 128 * GS_TP * 4;     // 69632 >= 2048 + 3*20480

__global__ __launch_bounds__(256, 2)
void gram_sym_kernel() {
    const int bx = blockIdx.x, by = blockIdx.y;
    if (by > bx) return;
    extern __shared__ char smem[];
    const int tid = threadIdx.x;
    const int warp = tid >> 5, lane = tid & 31;
    const int wm = warp >> 2, wn = warp & 3;
    const int g = lane >> 2, tc = lane & 3;
    const uint32_t sbase = smem_u32(smem);
    const ll z = blockIdx.z;
    const int bm = by * 128, bn = bx * 128;
    const bf16* Ag = g_hi + z * CS * CD + (ll)bm * CD;
    const bf16* Bg = g_hi + z * CS * CD + (ll)bn * CD;

    float* ssqr = (float*)smem;             // sq rows [bm..)
    float* ssqc = (float*)(smem + 512);     // sq cols [bn..)
    if (tid < 128) {
        ssqr[tid] = g_sq[z * CS + bm + tid];
        ssqc[tid] = g_sq[z * CS + bn + tid];
    }

    float acc[4][4][4];
    #pragma unroll
    for (int i = 0; i < 4; i++)
        #pragma unroll
        for (int j = 0; j < 4; j++)
            #pragma unroll
            for (int c = 0; c < 4; c++) acc[i][j][c] = 0.f;

    const int lr = tid >> 2;
    const int lc = (tid & 3) << 3;
    const int lrow = lane & 7, lm = lane >> 3;
    uint32_t aoff[4], boff[4];
    #pragma unroll
    for (int mt = 0; mt < 4; mt++)
        aoff[mt] = (uint32_t)((wm * 64 + mt * 16 + (lm & 1) * 8 + lrow) * ST_ROWB
                              + (lm >> 1) * 16);
    #pragma unroll
    for (int nt = 0; nt < 4; nt++)
        boff[nt] = (uint32_t)((wn * 32 + nt * 8 + lrow) * ST_ROWB + (lm & 1) * 16);

    auto load_stage = [&](int i, int s) {
        if (i < 8) {
            const int k0 = i << 5;
            uint32_t sa = sbase + GS_SOFF + s * ST_BYTES;
            uint32_t sb = sa + ST_HALF;
            #pragma unroll
            for (int j = 0; j < 2; j++) {
                int r = lr + j * 64;
                cp_async16(sa + r * ST_ROWB + lc * 2, Ag + (ll)r * CD + k0 + lc);
                cp_async16(sb + r * ST_ROWB + lc * 2, Bg + (ll)r * CD + k0 + lc);
            }
        }
        cp_commit();
    };

    load_stage(0, 0);
    load_stage(1, 1);

    for (int i = 0; i < 8; i++) {
        cp_wait1();
        __syncthreads();
        load_stage(i + 2, (i + 2) % 3);
        const uint32_t stg = sbase + GS_SOFF + (i % 3) * ST_BYTES;
        #pragma unroll
        for (int ks = 0; ks < 2; ks++) {
            unsigned a_r[4][4], b_r[4][2];
            #pragma unroll
            for (int mt = 0; mt < 4; mt++)
                ldsm_x4(a_r[mt], stg + aoff[mt] + ks * 32);
            #pragma unroll
            for (int nt = 0; nt < 4; nt++)
                ldsm_x2(b_r[nt], stg + ST_HALF + boff[nt] + ks * 32);
            #pragma unroll
            for (int mt = 0; mt < 4; mt++)
                #pragma unroll
                for (int nt = 0; nt < 4; nt++)
                    MMA_BF16(acc[mt][nt], a_r[mt], b_r[nt]);
        }
    }
    cp_wait0();
    __syncthreads();   // stage smem dead; ssqr/ssqc ready

    const bool diag = (bx == by);
    u32* st = (u32*)(smem + GS_SOFF);
    u32* Gk = g_gramk + (size_t)z * CS * CS;

    #pragma unroll
    for (int mt = 0; mt < 4; mt++) {
        #pragma unroll
        for (int nt = 0; nt < 4; nt++) {
            int lcol = wn * 32 + nt * 8 + tc * 2;
            #pragma unroll
            for (int h = 0; h < 2; h++) {
                int rl = wm * 64 + mt * 16 + g + h * 8;      // local row
                float v0 = acc[mt][nt][h * 2 + 0];
                float v1 = acc[mt][nt][h * 2 + 1];
                u32 kn0 = (key_xform(ssqc[lcol]     - 2.0f * v0) & 0xFFFFF000u) | (u32)(bn + lcol);
                u32 kn1 = (key_xform(ssqc[lcol + 1] - 2.0f * v1) & 0xFFFFF000u) | (u32)(bn + lcol + 1);
                *(uint2*)(Gk + (ll)(bm + rl) * CS + bn + lcol) = make_uint2(kn0, kn1);
                if (!diag) {
                    u32 kt0 = (key_xform(ssqr[rl] - 2.0f * v0) & 0xFFFFF000u) | (u32)(bm + rl);
                    u32 kt1 = (key_xform(ssqr[rl] - 2.0f * v1) & 0xFFFFF000u) | (u32)(bm + rl);
                    st[lcol * GS_TP + rl]       = kt0;
                    st[(lcol + 1) * GS_TP + rl] = kt1;
                }
            }
        }
    }
    if (!diag) {
        __syncthreads();
        const int r = tid >> 1, half = tid & 1;              // r = local col index
        u32* dst = Gk + (ll)(bn + r) * CS + bm + half * 64;
        const uint4* src = (const uint4*)(st + r * GS_TP + half * 64);
        #pragma unroll
        for (int q = 0; q < 16; q++)
            ((uint4*)dst)[q] = src[q];
    }
}

// ---------------- pack + sq fused ----------------
__global__ __launch_bounds__(256)
void packsq_kernel(const float* __restrict__ x, float* __restrict__ pos) {
    const int p = blockIdx.x;
    const int t = threadIdx.x;
    const float* xr = x + (ll)p * CIN;
    float v = xr[3 + t];
    g_feat[(ll)p * CD + t] = v;
    g_hi[(ll)p * CD + t] = __float2bfloat16(v);
    if (t < 3) pos[p * 3 + t] = xr[t];
    float s = v * v;
    #pragma unroll
    for (int o = 16; o; o >>= 1) s += __shfl_xor_sync(0xFFFFFFFFu, s, o);
    __shared__ float ws[8];
    if ((t & 31) == 0) ws[t >> 5] = s;
    __syncthreads();
    if (t == 0) {
        float tot = 0.f;
        #pragma unroll
        for (int w = 0; w < 8; w++) tot += ws[w];
        g_sq[p] = tot;
    }
}

__global__ void wqk_prep_kernel(const float* __restrict__ wq, const float* __restrict__ wk,
                                const float* __restrict__ g1) {
    int r = blockIdx.x, c = threadIdx.x;
    float aq = 0.f, ak = 0.f;
    for (int k = 0; k < CT; k++) {
        float gv = g1[k * CT + c];
        aq += wq[r * CT + k] * gv;
        ak += wk[r * CT + k] * gv;
    }
    g_wT[4][c * CT + r] = __float2bfloat16(aq);
    g_wT[5][c * CT + r] = __float2bfloat16(ak);
}

__global__ void tconv4_kernel(const float* __restrict__ fc1, const float* __restrict__ wv,
                              const float* __restrict__ g2, const float* __restrict__ fc2) {
    int n = blockIdx.x, k = threadIdx.x, w = blockIdx.y;
    const float* src = (w == 0) ? fc1 : (w == 1) ? wv : (w == 2) ? g2 : fc2;
    g_wT[w][n * CT + k] = __float2bfloat16(src[k * CT + n]);
}

// ---------------- top-K over pre-packed u32 keys (vectorized loads) ----------------
__device__ __forceinline__ void ce32(u32& a, u32& b) { if (a > b) { u32 t = a; a = b; b = t; } }
__device__ __forceinline__ void bitonic_sort16(u32* k) {
    #pragma unroll
    for (int sz = 2; sz <= 16; sz <<= 1)
        #pragma unroll
        for (int j = sz >> 1; j > 0; j >>= 1)
            #pragma unroll
            for (int i = 0; i < 16; i++) {
                int l = i ^ j;
                if (l > i) {
                    if ((i & sz) == 0) ce32(k[i], k[l]);
                    else               ce32(k[l], k[i]);
                }
            }
}
__device__ __forceinline__ void bitonic_merge16(u32* k) {
    #pragma unroll
    for (int j = 8; j > 0; j >>= 1)
        #pragma unroll
        for (int i = 0; i < 16; i++)
            if ((i & j) == 0) ce32(k[i], k[i | j]);
}

__global__ __launch_bounds__(256)
void topk_kernel() {
    const int row = blockIdx.x;
    const uint4* __restrict__ G4 = (const uint4*)(g_gramk + (size_t)row * CS);
    const int t = threadIdx.x, lane = t & 31, warp = t >> 5;

    // thread t owns contiguous keys [16t, 16t+16): 4 x uint4
    u32 keys[16];
    #pragma unroll
    for (int q = 0; q < 4; q++) {
        uint4 v = G4[t * 4 + q];
        keys[q * 4 + 0] = v.x; keys[q * 4 + 1] = v.y;
        keys[q * 4 + 2] = v.z; keys[q * 4 + 3] = v.w;
    }
    bitonic_sort16(keys);
    #pragma unroll
    for (int d = 1; d < 32; d <<= 1) {
        u32 p[16];
        #pragma unroll
        for (int i = 0; i < 16; i++) p[i] = __shfl_xor_sync(0xFFFFFFFFu, keys[i], d);
        if ((lane & (2 * d - 1)) == 0) {
            #pragma unroll
            for (int i = 0; i < 16; i++) keys[i] = umin(keys[i], p[15 - i]);
            bitonic_merge16(keys);
        }
    }
    __shared__ u32 sk[8][16];
    if (lane == 0)
        #pragma unroll
        for (int i = 0; i < 16; i++) sk[warp][i] = keys[i];
    __syncthreads();
    if (warp == 0) {
        if (lane < 8)
            #pragma unroll
            for (int i = 0; i < 16; i++) keys[i] = sk[lane][i];
        #pragma unroll
        for (int d = 1; d < 8; d <<= 1) {
            u32 p[16];
            #pragma unroll
            for (int i = 0; i < 16; i++) p[i] = __shfl_xor_sync(0xFFFFFFFFu, keys[i], d);
            if (lane < 8 && (lane & (2 * d - 1)) == 0) {
                #pragma unroll
                for (int i = 0; i < 16; i++) keys[i] = umin(keys[i], p[15 - i]);
                bitonic_merge16(keys);
            }
        }
        if (lane == 0)
            #pragma unroll
            for (int i = 0; i < 16; i++) g_idx[row * CK + i] = (int)(keys[i] & 0xFFFu);
    }
}

// ---------------- t1 = relu(qg + g1_b - gather(kg bf16)) -> bf16 ----------------
__global__ __launch_bounds__(256)
void t1_kernel(const float* __restrict__ g1b) {
    const int bn = blockIdx.x;
    const int b = bn >> 12;
    const int t = threadIdx.x;
    __shared__ float qrow[CT];
    __shared__ int nb[CK];
    qrow[t] = g_qg[(ll)bn * CT + t] + g1b[t];
    if (t < CK) nb[t] = g_idx[bn * CK + t];
    __syncthreads();
    #pragma unroll
    for (int k = 0; k < CK; k++) {
        float v = qrow[t] - __bfloat162float(g_kgh[((ll)b * CS + nb[k]) * CT + t]);
        g_t1[((ll)bn * CK + k) * CT + t] = __float2bfloat16(v > 0.f ? v : 0.f);
    }
}

// ---------------- softmax over K + weighted gather-sum (v bf16) ----------------
__global__ __launch_bounds__(256)
void softmax_res_kernel() {
    const int bn = blockIdx.x;
    const int b = bn >> 12;
    const int t = threadIdx.x;
    __shared__ int nb[CK];
    if (t < CK) nb[t] = g_idx[bn * CK + t];
    __syncthreads();
    float lg[CK];
    float mx = -1e30f;
    #pragma unroll
    for (int k = 0; k < CK; k++) {
        lg[k] = __bfloat162float(g_attn[((ll)bn * CK + k) * CT + t]) * 0.0625f;
        mx = fmaxf(mx, lg[k]);
    }
    float se = 0.f;
    #pragma unroll
    for (int k = 0; k < CK; k++) { lg[k] = expf(lg[k] - mx); se += lg[k]; }
    const float inv = 1.f / se;
    float r = 0.f;
    #pragma unroll
    for (int k = 0; k < CK; k++)
        r += lg[k] * inv * __bfloat162float(g_vh[((ll)b * CS + nb[k]) * CT + t]);
    g_res[(ll)bn * CT + t] = __float2bfloat16(r);
}

// ---------------- launch ----------------
extern "C" void kernel_launch(void* const* d_in, const int* in_sizes, int n_in,
                              void* d_out, int out_size) {
    const float* x     = (const float*)d_in[0];
    const float* fc1_w = (const float*)d_in[1];
    const float* fc1_b = (const float*)d_in[2];
    const float* fc2_w = (const float*)d_in[3];
    const float* fc2_b = (const float*)d_in[4];
    const float* wq_w  = (const float*)d_in[5];
    const float* wk_w  = (const float*)d_in[6];
    const float* wv_w  = (const float*)d_in[7];
    const float* g1_w  = (const float*)d_in[8];
    const float* g1_b  = (const float*)d_in[9];
    const float* g2_w  = (const float*)d_in[10];
    const float* g2_b  = (const float*)d_in[11];

    float* out     = (float*)d_out;
    float* pos     = out;
    float* outMain = out + CB * CS * 3;

    bf16 *hi, *h, *kgh, *vh, *t1, *attn, *res, *wT;
    float *feat, *qg;
    cudaGetSymbolAddress((void**)&hi,   g_hi);
    cudaGetSymbolAddress((void**)&feat, g_feat);
    cudaGetSymbolAddress((void**)&h,    g_h);
    cudaGetSymbolAddress((void**)&qg,   g_qg);
    cudaGetSymbolAddress((void**)&kgh,  g_kgh);
    cudaGetSymbolAddress((void**)&vh,   g_vh);
    cudaGetSymbolAddress((void**)&t1,   g_t1);
    cudaGetSymbolAddress((void**)&attn, g_attn);
    cudaGetSymbolAddress((void**)&res,  g_res);
    cudaGetSymbolAddress((void**)&wT,   g_wT);

    bf16* fc1T = wT + 0 * CT * CT;
    bf16* wvT  = wT + 1 * CT * CT;
    bf16* g2T  = wT + 2 * CT * CT;
    bf16* fc2T = wT + 3 * CT * CT;
    bf16* WqgT = wT + 4 * CT * CT;
    bf16* WkgT = wT + 5 * CT * CT;

    cudaFuncSetAttribute(mma_gemm<0, false, false>, cudaFuncAttributeMaxDynamicSharedMemorySize, SMEM_MMA);
    cudaFuncSetAttribute(mma_gemm<1, false, false>, cudaFuncAttributeMaxDynamicSharedMemorySize, SMEM_MMA);
    cudaFuncSetAttribute(mma_gemm<1, true, false>,  cudaFuncAttributeMaxDynamicSharedMemorySize, SMEM_MMA);
    cudaFuncSetAttribute(mma_gemm<0, true, true>,   cudaFuncAttributeMaxDynamicSharedMemorySize, SMEM_MMA);
    cudaFuncSetAttribute(gram_sym_kernel, cudaFuncAttributeMaxDynamicSharedMemorySize, GS_SMEM);

    // 1) pack + norms + weight prep
    packsq_kernel<<<CB * CS, 256>>>(x, pos);
    wqk_prep_kernel<<<CT, CT>>>(wq_w, wk_w, g1_w);
    {
        dim3 g(CT, 4, 1);
        tconv4_kernel<<<g, CT>>>(fc1_w, wv_w, g2_w, fc2_w);
    }

    // 2) symmetric Gram -> packed u32 keys (upper-triangle tiles)
    {
        dim3 g(CS / 128, CS / 128, CB);
        gram_sym_kernel<<<g, 256, GS_SMEM>>>();
    }
    // 3) topk (vectorized key loads)
    topk_kernel<<<CB * CS, 256>>>();

    // 4) h = bf16(feat @ fc1 + b1); qg (f32), kg (bf16), v (bf16)
    {
        dim3 g(CT / 128, (CB * CS) / 128, 1);
        mma_gemm<1, true, false><<<g, 256, SMEM_MMA>>>(
            hi, fc1T, fc1_b, nullptr, nullptr, h, CT, CD, CD, 0, 0, 0);
        mma_gemm<0, false, false><<<g, 256, SMEM_MMA>>>(
            h, WqgT, nullptr, nullptr, qg, nullptr, CT, CT, CT, 0, 0, 0);
        mma_gemm<1, false, false><<<g, 256, SMEM_MMA>>>(
            h, WkgT, nullptr, nullptr, nullptr, kgh, CT, CT, CT, 0, 0, 0);
        mma_gemm<1, false, false><<<g, 256, SMEM_MMA>>>(
            h, wvT, nullptr, nullptr, nullptr, vh, CT, CT, CT, 0, 0, 0);
    }

    // 5) t1 = relu(qg + g1_b - gather(kg))
    t1_kernel<<<CB * CS, 256>>>(g1_b);

    // 6) attn = bf16(t1 @ g2 + g2_b)
    {
        dim3 g(CT / 128, (CB * CS * CK) / 128, 1);
        mma_gemm<1, true, false><<<g, 256, SMEM_MMA>>>(
            t1, g2T, g2_b, nullptr, nullptr, attn, CT, CT, CT, 0, 0, 0);
    }

    // 7) softmax + weighted v
    softmax_res_kernel<<<CB * CS, 256>>>();

    // 8) out = res @ fc2 + fc2_b + feat
    {
        dim3 g(CD / 128, (CB * CS) / 128, 1);
        mma_gemm<0, true, true><<<g, 256, SMEM_MMA>>>(
            res, fc2T, fc2_b, feat, outMain, nullptr, CD, CT, CT, 0, 0, 0);
    }
}

// round 15
// speedup vs baseline: 1.5336x; 1.5336x over previous
#include <cuda_runtime.h>
#include <cuda_bf16.h>
#include <cstdint>

#define CB 4
#define CS 4096
#define CD 256
#define CT 256
#define CK 16
#define CIN 259

typedef long long ll;
typedef unsigned u32;
typedef __nv_bfloat16 bf16;

// ---------------- device scratch ----------------
__device__ bf16  g_hi[(size_t)CB * CS * CD];
__device__ float g_feat[CB * CS * CD];
__device__ float g_sq[CB * CS];
__device__ u32   g_gramk[(size_t)CB * CS * CS];        // 256MB packed keys
__device__ int   g_idx[CB * CS * CK];
__device__ bf16  g_h[CB * CS * CT];
__device__ float g_qg[CB * CS * CT];
__device__ bf16  g_kgh[CB * CS * CT];
__device__ bf16  g_vh[CB * CS * CT];
__device__ bf16  g_t1[(size_t)CB * CS * CK * CT];      // 128MB
__device__ bf16  g_attn[(size_t)CB * CS * CK * CT];    // 128MB
__device__ bf16  g_res[CB * CS * CT];
// transposed bf16 weights: 0=fc1,1=wv,2=g2,3=fc2,4=Wqg,5=Wkg
__device__ bf16  g_wT[6][CT * CT];

// ---------------- helpers ----------------
__device__ __forceinline__ uint32_t smem_u32(const void* p) {
    return (uint32_t)__cvta_generic_to_shared(p);
}
__device__ __forceinline__ void cp_async16(uint32_t s, const void* g) {
    asm volatile("cp.async.cg.shared.global [%0], [%1], 16;" :: "r"(s), "l"(g));
}
__device__ __forceinline__ void cp_commit() {
    asm volatile("cp.async.commit_group;" ::: "memory");
}
__device__ __forceinline__ void cp_wait1() {
    asm volatile("cp.async.wait_group 1;" ::: "memory");
}
__device__ __forceinline__ void cp_wait0() {
    asm volatile("cp.async.wait_group 0;" ::: "memory");
}
__device__ __forceinline__ void ldsm_x4(unsigned* r, uint32_t addr) {
    asm volatile("ldmatrix.sync.aligned.m8n8.x4.shared.b16 {%0,%1,%2,%3}, [%4];"
                 : "=r"(r[0]), "=r"(r[1]), "=r"(r[2]), "=r"(r[3]) : "r"(addr));
}
__device__ __forceinline__ void ldsm_x2(unsigned* r, uint32_t addr) {
    asm volatile("ldmatrix.sync.aligned.m8n8.x2.shared.b16 {%0,%1}, [%2];"
                 : "=r"(r[0]), "=r"(r[1]) : "r"(addr));
}
#define MMA_BF16(acc, ar, br) \
    asm volatile( \
        "mma.sync.aligned.m16n8k16.row.col.f32.bf16.bf16.f32 " \
        "{%0,%1,%2,%3}, {%4,%5,%6,%7}, {%8,%9}, {%0,%1,%2,%3};" \
        : "+f"((acc)[0]), "+f"((acc)[1]), "+f"((acc)[2]), "+f"((acc)[3]) \
        : "r"((ar)[0]), "r"((ar)[1]), "r"((ar)[2]), "r"((ar)[3]), \
          "r"((br)[0]), "r"((br)[1]))

__device__ __forceinline__ u32 key_xform(float sc) {
    u32 u = __float_as_uint(sc);
    return (u & 0x80000000u) ? ~u : (u | 0x80000000u);
}

// ---------------- pipelined bf16 HMMA GEMM with ldmatrix (3-stage) ----------------
static constexpr int ST_ROWB = 80;
static constexpr int ST_HALF = 128 * ST_ROWB;
static constexpr int ST_BYTES = 2 * ST_HALF;
static constexpr int SOFF_STG = 1024;
static constexpr int SMEM_MMA = SOFF_STG + 3 * ST_BYTES;

template <int OUT_BF16, bool BIAS, bool ADD_RES>
__global__ __launch_bounds__(256, 2)
void mma_gemm(const bf16* __restrict__ A, const bf16* __restrict__ B,
              const float* __restrict__ bias, const float* __restrict__ Rres,
              float* __restrict__ Cf, bf16* __restrict__ Ch,
              int N, int Kd, int lda, ll sA, ll sB, ll sC) {
    extern __shared__ char smem[];
    const int tid = threadIdx.x;
    const int warp = tid >> 5, lane = tid & 31;
    const int wm = warp >> 2, wn = warp & 3;
    const int g = lane >> 2, tc = lane & 3;
    const uint32_t sbase = smem_u32(smem);
    const ll z = blockIdx.z;
    const int bm = blockIdx.y * 128, bn = blockIdx.x * 128;
    const bf16* Ag = A + z * sA + (ll)bm * lda;
    const bf16* Bg = B + z * sB + (ll)bn * Kd;

    float* sbias = (float*)smem;
    if (BIAS && tid < 128) sbias[tid] = bias[bn + tid];

    float acc[4][4][4];
    #pragma unroll
    for (int i = 0; i < 4; i++)
        #pragma unroll
        for (int j = 0; j < 4; j++)
            #pragma unroll
            for (int c = 0; c < 4; c++) acc[i][j][c] = 0.f;

    const int nch = Kd >> 5;
    const int lr = tid >> 2;
    const int lc = (tid & 3) << 3;

    const int lrow = lane & 7, lm = lane >> 3;
    uint32_t aoff[4], boff[4];
    #pragma unroll
    for (int mt = 0; mt < 4; mt++)
        aoff[mt] = (uint32_t)((wm * 64 + mt * 16 + (lm & 1) * 8 + lrow) * ST_ROWB
                              + (lm >> 1) * 16);
    #pragma unroll
    for (int nt = 0; nt < 4; nt++)
        boff[nt] = (uint32_t)((wn * 32 + nt * 8 + lrow) * ST_ROWB + (lm & 1) * 16);

    auto load_stage = [&](int i, int s) {
        if (i < nch) {
            const int k0 = i << 5;
            uint32_t sa = sbase + SOFF_STG + s * ST_BYTES;
            uint32_t sb = sa + ST_HALF;
            #pragma unroll
            for (int j = 0; j < 2; j++) {
                int r = lr + j * 64;
                cp_async16(sa + r * ST_ROWB + lc * 2, Ag + (ll)r * lda + k0 + lc);
                cp_async16(sb + r * ST_ROWB + lc * 2, Bg + (ll)r * Kd + k0 + lc);
            }
        }
        cp_commit();
    };

    load_stage(0, 0);
    load_stage(1, 1);

    for (int i = 0; i < nch; i++) {
        cp_wait1();
        __syncthreads();
        load_stage(i + 2, (i + 2) % 3);

        const uint32_t stg = sbase + SOFF_STG + (i % 3) * ST_BYTES;
        #pragma unroll
        for (int ks = 0; ks < 2; ks++) {
            unsigned a_r[4][4], b_r[4][2];
            #pragma unroll
            for (int mt = 0; mt < 4; mt++)
                ldsm_x4(a_r[mt], stg + aoff[mt] + ks * 32);
            #pragma unroll
            for (int nt = 0; nt < 4; nt++)
                ldsm_x2(b_r[nt], stg + ST_HALF + boff[nt] + ks * 32);
            #pragma unroll
            for (int mt = 0; mt < 4; mt++)
                #pragma unroll
                for (int nt = 0; nt < 4; nt++)
                    MMA_BF16(acc[mt][nt], a_r[mt], b_r[nt]);
        }
    }

    #pragma unroll
    for (int mt = 0; mt < 4; mt++) {
        int r0 = bm + wm * 64 + mt * 16 + g;
        #pragma unroll
        for (int nt = 0; nt < 4; nt++) {
            int lcol = wn * 32 + nt * 8 + tc * 2;
            int c0 = bn + lcol;
            #pragma unroll
            for (int h = 0; h < 2; h++) {
                int rr = r0 + h * 8;
                float v0 = acc[mt][nt][h * 2 + 0];
                float v1 = acc[mt][nt][h * 2 + 1];
                if (BIAS) { v0 += sbias[lcol]; v1 += sbias[lcol + 1]; }
                if (ADD_RES) {
                    v0 += Rres[(ll)rr * N + c0];
                    v1 += Rres[(ll)rr * N + c0 + 1];
                }
                if (OUT_BF16) {
                    __nv_bfloat162 pk;
                    pk.x = __float2bfloat16(v0);
                    pk.y = __float2bfloat16(v1);
                    *(__nv_bfloat162*)(Ch + z * sC + (ll)rr * N + c0) = pk;
                } else {
                    *(float2*)(Cf + z * sC + (ll)rr * N + c0) = make_float2(v0, v1);
                }
            }
        }
    }
}

// ---------------- symmetric Gram -> packed u32 keys (upper-triangle tiles) ----------------
static constexpr int GS_SOFF = 2048;
static constexpr int GS_TP = 132;                             // u32 pitch (528B)
static constexpr int GS_SMEM = GS_SOFF + 128 * GS_TP * 4;     // 69632 >= 2048 + 3*20480

__global__ __launch_bounds__(256, 2)
void gram_sym_kernel() {
    const int bx = blockIdx.x, by = blockIdx.y;
    if (by > bx) return;
    extern __shared__ char smem[];
    const int tid = threadIdx.x;
    const int warp = tid >> 5, lane = tid & 31;
    const int wm = warp >> 2, wn = warp & 3;
    const int g = lane >> 2, tc = lane & 3;
    const uint32_t sbase = smem_u32(smem);
    const ll z = blockIdx.z;
    const int bm = by * 128, bn = bx * 128;
    const bf16* Ag = g_hi + z * CS * CD + (ll)bm * CD;
    const bf16* Bg = g_hi + z * CS * CD + (ll)bn * CD;

    float* ssqr = (float*)smem;             // sq rows [bm..)
    float* ssqc = (float*)(smem + 512);     // sq cols [bn..)
    if (tid < 128) {
        ssqr[tid] = g_sq[z * CS + bm + tid];
        ssqc[tid] = g_sq[z * CS + bn + tid];
    }

    float acc[4][4][4];
    #pragma unroll
    for (int i = 0; i < 4; i++)
        #pragma unroll
        for (int j = 0; j < 4; j++)
            #pragma unroll
            for (int c = 0; c < 4; c++) acc[i][j][c] = 0.f;

    const int lr = tid >> 2;
    const int lc = (tid & 3) << 3;
    const int lrow = lane & 7, lm = lane >> 3;
    uint32_t aoff[4], boff[4];
    #pragma unroll
    for (int mt = 0; mt < 4; mt++)
        aoff[mt] = (uint32_t)((wm * 64 + mt * 16 + (lm & 1) * 8 + lrow) * ST_ROWB
                              + (lm >> 1) * 16);
    #pragma unroll
    for (int nt = 0; nt < 4; nt++)
        boff[nt] = (uint32_t)((wn * 32 + nt * 8 + lrow) * ST_ROWB + (lm & 1) * 16);

    auto load_stage = [&](int i, int s) {
        if (i < 8) {
            const int k0 = i << 5;
            uint32_t sa = sbase + GS_SOFF + s * ST_BYTES;
            uint32_t sb = sa + ST_HALF;
            #pragma unroll
            for (int j = 0; j < 2; j++) {
                int r = lr + j * 64;
                cp_async16(sa + r * ST_ROWB + lc * 2, Ag + (ll)r * CD + k0 + lc);
                cp_async16(sb + r * ST_ROWB + lc * 2, Bg + (ll)r * CD + k0 + lc);
            }
        }
        cp_commit();
    };

    load_stage(0, 0);
    load_stage(1, 1);

    for (int i = 0; i < 8; i++) {
        cp_wait1();
        __syncthreads();
        load_stage(i + 2, (i + 2) % 3);
        const uint32_t stg = sbase + GS_SOFF + (i % 3) * ST_BYTES;
        #pragma unroll
        for (int ks = 0; ks < 2; ks++) {
            unsigned a_r[4][4], b_r[4][2];
            #pragma unroll
            for (int mt = 0; mt < 4; mt++)
                ldsm_x4(a_r[mt], stg + aoff[mt] + ks * 32);
            #pragma unroll
            for (int nt = 0; nt < 4; nt++)
                ldsm_x2(b_r[nt], stg + ST_HALF + boff[nt] + ks * 32);
            #pragma unroll
            for (int mt = 0; mt < 4; mt++)
                #pragma unroll
                for (int nt = 0; nt < 4; nt++)
                    MMA_BF16(acc[mt][nt], a_r[mt], b_r[nt]);
        }
    }
    cp_wait0();
    __syncthreads();   // stage smem dead; ssqr/ssqc ready

    const bool diag = (bx == by);
    u32* st = (u32*)(smem + GS_SOFF);
    u32* Gk = g_gramk + (size_t)z * CS * CS;

    #pragma unroll
    for (int mt = 0; mt < 4; mt++) {
        #pragma unroll
        for (int nt = 0; nt < 4; nt++) {
            int lcol = wn * 32 + nt * 8 + tc * 2;
            #pragma unroll
            for (int h = 0; h < 2; h++) {
                int rl = wm * 64 + mt * 16 + g + h * 8;      // local row
                float v0 = acc[mt][nt][h * 2 + 0];
                float v1 = acc[mt][nt][h * 2 + 1];
                u32 kn0 = (key_xform(ssqc[lcol]     - 2.0f * v0) & 0xFFFFF000u) | (u32)(bn + lcol);
                u32 kn1 = (key_xform(ssqc[lcol + 1] - 2.0f * v1) & 0xFFFFF000u) | (u32)(bn + lcol + 1);
                *(uint2*)(Gk + (ll)(bm + rl) * CS + bn + lcol) = make_uint2(kn0, kn1);
                if (!diag) {
                    u32 kt0 = (key_xform(ssqr[rl] - 2.0f * v0) & 0xFFFFF000u) | (u32)(bm + rl);
                    u32 kt1 = (key_xform(ssqr[rl] - 2.0f * v1) & 0xFFFFF000u) | (u32)(bm + rl);
                    st[lcol * GS_TP + rl]       = kt0;
                    st[(lcol + 1) * GS_TP + rl] = kt1;
                }
            }
        }
    }
    if (!diag) {
        __syncthreads();
        const int r = tid >> 1, half = tid & 1;              // r = local col index
        u32* dst = Gk + (ll)(bn + r) * CS + bm + half * 64;
        const uint4* src = (const uint4*)(st + r * GS_TP + half * 64);
        #pragma unroll
        for (int q = 0; q < 16; q++)
            ((uint4*)dst)[q] = src[q];
    }
}

// ---------------- pack + sq fused ----------------
__global__ __launch_bounds__(256)
void packsq_kernel(const float* __restrict__ x, float* __restrict__ pos) {
    const int p = blockIdx.x;
    const int t = threadIdx.x;
    const float* xr = x + (ll)p * CIN;
    float v = xr[3 + t];
    g_feat[(ll)p * CD + t] = v;
    g_hi[(ll)p * CD + t] = __float2bfloat16(v);
    if (t < 3) pos[p * 3 + t] = xr[t];
    float s = v * v;
    #pragma unroll
    for (int o = 16; o; o >>= 1) s += __shfl_xor_sync(0xFFFFFFFFu, s, o);
    __shared__ float ws[8];
    if ((t & 31) == 0) ws[t >> 5] = s;
    __syncthreads();
    if (t == 0) {
        float tot = 0.f;
        #pragma unroll
        for (int w = 0; w < 8; w++) tot += ws[w];
        g_sq[p] = tot;
    }
}

__global__ void wqk_prep_kernel(const float* __restrict__ wq, const float* __restrict__ wk,
                                const float* __restrict__ g1) {
    int r = blockIdx.x, c = threadIdx.x;
    float aq = 0.f, ak = 0.f;
    for (int k = 0; k < CT; k++) {
        float gv = g1[k * CT + c];
        aq += wq[r * CT + k] * gv;
        ak += wk[r * CT + k] * gv;
    }
    g_wT[4][c * CT + r] = __float2bfloat16(aq);
    g_wT[5][c * CT + r] = __float2bfloat16(ak);
}

__global__ void tconv4_kernel(const float* __restrict__ fc1, const float* __restrict__ wv,
                              const float* __restrict__ g2, const float* __restrict__ fc2) {
    int n = blockIdx.x, k = threadIdx.x, w = blockIdx.y;
    const float* src = (w == 0) ? fc1 : (w == 1) ? wv : (w == 2) ? g2 : fc2;
    g_wT[w][n * CT + k] = __float2bfloat16(src[k * CT + n]);
}

// ---------------- top-K over pre-packed u32 keys (coalesced uint4 loads) ----------------
__device__ __forceinline__ void ce32(u32& a, u32& b) { if (a > b) { u32 t = a; a = b; b = t; } }
__device__ __forceinline__ void bitonic_sort16(u32* k) {
    #pragma unroll
    for (int sz = 2; sz <= 16; sz <<= 1)
        #pragma unroll
        for (int j = sz >> 1; j > 0; j >>= 1)
            #pragma unroll
            for (int i = 0; i < 16; i++) {
                int l = i ^ j;
                if (l > i) {
                    if ((i & sz) == 0) ce32(k[i], k[l]);
                    else               ce32(k[l], k[i]);
                }
            }
}
__device__ __forceinline__ void bitonic_merge16(u32* k) {
    #pragma unroll
    for (int j = 8; j > 0; j >>= 1)
        #pragma unroll
        for (int i = 0; i < 16; i++)
            if ((i & j) == 0) ce32(k[i], k[i | j]);
}

__global__ __launch_bounds__(256)
void topk_kernel() {
    const int row = blockIdx.x;
    const uint4* __restrict__ G4 = (const uint4*)(g_gramk + (size_t)row * CS);
    const int t = threadIdx.x, lane = t & 31, warp = t >> 5;

    // coalesced: thread t loads uint4 at q*256 + t  (lanes contiguous per instr)
    u32 keys[16];
    #pragma unroll
    for (int q = 0; q < 4; q++) {
        uint4 v = G4[q * 256 + t];
        keys[q * 4 + 0] = v.x; keys[q * 4 + 1] = v.y;
        keys[q * 4 + 2] = v.z; keys[q * 4 + 3] = v.w;
    }
    bitonic_sort16(keys);
    #pragma unroll
    for (int d = 1; d < 32; d <<= 1) {
        u32 p[16];
        #pragma unroll
        for (int i = 0; i < 16; i++) p[i] = __shfl_xor_sync(0xFFFFFFFFu, keys[i], d);
        if ((lane & (2 * d - 1)) == 0) {
            #pragma unroll
            for (int i = 0; i < 16; i++) keys[i] = umin(keys[i], p[15 - i]);
            bitonic_merge16(keys);
        }
    }
    __shared__ u32 sk[8][16];
    if (lane == 0)
        #pragma unroll
        for (int i = 0; i < 16; i++) sk[warp][i] = keys[i];
    __syncthreads();
    if (warp == 0) {
        if (lane < 8)
            #pragma unroll
            for (int i = 0; i < 16; i++) keys[i] = sk[lane][i];
        #pragma unroll
        for (int d = 1; d < 8; d <<= 1) {
            u32 p[16];
            #pragma unroll
            for (int i = 0; i < 16; i++) p[i] = __shfl_xor_sync(0xFFFFFFFFu, keys[i], d);
            if (lane < 8 && (lane & (2 * d - 1)) == 0) {
                #pragma unroll
                for (int i = 0; i < 16; i++) keys[i] = umin(keys[i], p[15 - i]);
                bitonic_merge16(keys);
            }
        }
        if (lane == 0)
            #pragma unroll
            for (int i = 0; i < 16; i++) g_idx[row * CK + i] = (int)(keys[i] & 0xFFFu);
    }
}

// ---------------- t1 = relu(qg + g1_b - gather(kg bf16)) -> bf16 ----------------
__global__ __launch_bounds__(256)
void t1_kernel(const float* __restrict__ g1b) {
    const int bn = blockIdx.x;
    const int b = bn >> 12;
    const int t = threadIdx.x;
    __shared__ float qrow[CT];
    __shared__ int nb[CK];
    qrow[t] = g_qg[(ll)bn * CT + t] + g1b[t];
    if (t < CK) nb[t] = g_idx[bn * CK + t];
    __syncthreads();
    #pragma unroll
    for (int k = 0; k < CK; k++) {
        float v = qrow[t] - __bfloat162float(g_kgh[((ll)b * CS + nb[k]) * CT + t]);
        g_t1[((ll)bn * CK + k) * CT + t] = __float2bfloat16(v > 0.f ? v : 0.f);
    }
}

// ---------------- softmax over K + weighted gather-sum (v bf16) ----------------
__global__ __launch_bounds__(256)
void softmax_res_kernel() {
    const int bn = blockIdx.x;
    const int b = bn >> 12;
    const int t = threadIdx.x;
    __shared__ int nb[CK];
    if (t < CK) nb[t] = g_idx[bn * CK + t];
    __syncthreads();
    float lg[CK];
    float mx = -1e30f;
    #pragma unroll
    for (int k = 0; k < CK; k++) {
        lg[k] = __bfloat162float(g_attn[((ll)bn * CK + k) * CT + t]) * 0.0625f;
        mx = fmaxf(mx, lg[k]);
    }
    float se = 0.f;
    #pragma unroll
    for (int k = 0; k < CK; k++) { lg[k] = expf(lg[k] - mx); se += lg[k]; }
    const float inv = 1.f / se;
    float r = 0.f;
    #pragma unroll
    for (int k = 0; k < CK; k++)
        r += lg[k] * inv * __bfloat162float(g_vh[((ll)b * CS + nb[k]) * CT + t]);
    g_res[(ll)bn * CT + t] = __float2bfloat16(r);
}

// ---------------- launch ----------------
extern "C" void kernel_launch(void* const* d_in, const int* in_sizes, int n_in,
                              void* d_out, int out_size) {
    const float* x     = (const float*)d_in[0];
    const float* fc1_w = (const float*)d_in[1];
    const float* fc1_b = (const float*)d_in[2];
    const float* fc2_w = (const float*)d_in[3];
    const float* fc2_b = (const float*)d_in[4];
    const float* wq_w  = (const float*)d_in[5];
    const float* wk_w  = (const float*)d_in[6];
    const float* wv_w  = (const float*)d_in[7];
    const float* g1_w  = (const float*)d_in[8];
    const float* g1_b  = (const float*)d_in[9];
    const float* g2_w  = (const float*)d_in[10];
    const float* g2_b  = (const float*)d_in[11];

    float* out     = (float*)d_out;
    float* pos     = out;
    float* outMain = out + CB * CS * 3;

    bf16 *hi, *h, *kgh, *vh, *t1, *attn, *res, *wT;
    float *feat, *qg;
    cudaGetSymbolAddress((void**)&hi,   g_hi);
    cudaGetSymbolAddress((void**)&feat, g_feat);
    cudaGetSymbolAddress((void**)&h,    g_h);
    cudaGetSymbolAddress((void**)&qg,   g_qg);
    cudaGetSymbolAddress((void**)&kgh,  g_kgh);
    cudaGetSymbolAddress((void**)&vh,   g_vh);
    cudaGetSymbolAddress((void**)&t1,   g_t1);
    cudaGetSymbolAddress((void**)&attn, g_attn);
    cudaGetSymbolAddress((void**)&res,  g_res);
    cudaGetSymbolAddress((void**)&wT,   g_wT);

    bf16* fc1T = wT + 0 * CT * CT;
    bf16* wvT  = wT + 1 * CT * CT;
    bf16* g2T  = wT + 2 * CT * CT;
    bf16* fc2T = wT + 3 * CT * CT;
    bf16* WqgT = wT + 4 * CT * CT;
    bf16* WkgT = wT + 5 * CT * CT;

    cudaFuncSetAttribute(mma_gemm<0, false, false>, cudaFuncAttributeMaxDynamicSharedMemorySize, SMEM_MMA);
    cudaFuncSetAttribute(mma_gemm<1, false, false>, cudaFuncAttributeMaxDynamicSharedMemorySize, SMEM_MMA);
    cudaFuncSetAttribute(mma_gemm<1, true, false>,  cudaFuncAttributeMaxDynamicSharedMemorySize, SMEM_MMA);
    cudaFuncSetAttribute(mma_gemm<0, true, true>,   cudaFuncAttributeMaxDynamicSharedMemorySize, SMEM_MMA);
    cudaFuncSetAttribute(gram_sym_kernel, cudaFuncAttributeMaxDynamicSharedMemorySize, GS_SMEM);

    // 1) pack + norms + weight prep
    packsq_kernel<<<CB * CS, 256>>>(x, pos);
    wqk_prep_kernel<<<CT, CT>>>(wq_w, wk_w, g1_w);
    {
        dim3 g(CT, 4, 1);
        tconv4_kernel<<<g, CT>>>(fc1_w, wv_w, g2_w, fc2_w);
    }

    // 2) symmetric Gram -> packed u32 keys (upper-triangle tiles)
    {
        dim3 g(CS / 128, CS / 128, CB);
        gram_sym_kernel<<<g, 256, GS_SMEM>>>();
    }
    // 3) topk (coalesced vectorized key loads)
    topk_kernel<<<CB * CS, 256>>>();

    // 4) h = bf16(feat @ fc1 + b1); qg (f32), kg (bf16), v (bf16)
    {
        dim3 g(CT / 128, (CB * CS) / 128, 1);
        mma_gemm<1, true, false><<<g, 256, SMEM_MMA>>>(
            hi, fc1T, fc1_b, nullptr, nullptr, h, CT, CD, CD, 0, 0, 0);
        mma_gemm<0, false, false><<<g, 256, SMEM_MMA>>>(
            h, WqgT, nullptr, nullptr, qg, nullptr, CT, CT, CT, 0, 0, 0);
        mma_gemm<1, false, false><<<g, 256, SMEM_MMA>>>(
            h, WkgT, nullptr, nullptr, nullptr, kgh, CT, CT, CT, 0, 0, 0);
        mma_gemm<1, false, false><<<g, 256, SMEM_MMA>>>(
            h, wvT, nullptr, nullptr, nullptr, vh, CT, CT, CT, 0, 0, 0);
    }

    // 5) t1 = relu(qg + g1_b - gather(kg))
    t1_kernel<<<CB * CS, 256>>>(g1_b);

    // 6) attn = bf16(t1 @ g2 + g2_b)
    {
        dim3 g(CT / 128, (CB * CS * CK) / 128, 1);
        mma_gemm<1, true, false><<<g, 256, SMEM_MMA>>>(
            t1, g2T, g2_b, nullptr, nullptr, attn, CT, CT, CT, 0, 0, 0);
    }

    // 7) softmax + weighted v
    softmax_res_kernel<<<CB * CS, 256>>>();

    // 8) out = res @ fc2 + fc2_b + feat
    {
        dim3 g(CD / 128, (CB * CS) / 128, 1);
        mma_gemm<0, true, true><<<g, 256, SMEM_MMA>>>(
            res, fc2T, fc2_b, feat, outMain, nullptr, CD, CT, CT, 0, 0, 0);
    }
}

// round 16
// speedup vs baseline: 1.5541x; 1.0133x over previous
#include <cuda_runtime.h>
#include <cuda_bf16.h>
#include <cstdint>

#define CB 4
#define CS 4096
#define CD 256
#define CT 256
#define CK 16
#define CIN 259

typedef long long ll;
typedef unsigned u32;
typedef __nv_bfloat16 bf16;

// ---------------- device scratch ----------------
__device__ bf16  g_hi[(size_t)CB * CS * CD];
__device__ float g_feat[CB * CS * CD];
__device__ float g_sq[CB * CS];
__device__ u32   g_gramk[(size_t)CB * CS * CS];        // 256MB packed keys
__device__ int   g_idx[CB * CS * CK];
__device__ bf16  g_h[CB * CS * CT];
__device__ float g_qg[CB * CS * CT];
__device__ bf16  g_kgh[CB * CS * CT];
__device__ bf16  g_vh[CB * CS * CT];
__device__ bf16  g_t1[(size_t)CB * CS * CK * CT];      // 128MB
__device__ bf16  g_res[CB * CS * CT];
// transposed bf16 weights: 0=fc1,1=wv,2=g2,3=fc2,4=Wqg,5=Wkg
__device__ bf16  g_wT[6][CT * CT];

// ---------------- helpers ----------------
__device__ __forceinline__ uint32_t smem_u32(const void* p) {
    return (uint32_t)__cvta_generic_to_shared(p);
}
__device__ __forceinline__ void cp_async16(uint32_t s, const void* g) {
    asm volatile("cp.async.cg.shared.global [%0], [%1], 16;" :: "r"(s), "l"(g));
}
__device__ __forceinline__ void cp_commit() {
    asm volatile("cp.async.commit_group;" ::: "memory");
}
__device__ __forceinline__ void cp_wait1() {
    asm volatile("cp.async.wait_group 1;" ::: "memory");
}
__device__ __forceinline__ void cp_wait0() {
    asm volatile("cp.async.wait_group 0;" ::: "memory");
}
__device__ __forceinline__ void ldsm_x4(unsigned* r, uint32_t addr) {
    asm volatile("ldmatrix.sync.aligned.m8n8.x4.shared.b16 {%0,%1,%2,%3}, [%4];"
                 : "=r"(r[0]), "=r"(r[1]), "=r"(r[2]), "=r"(r[3]) : "r"(addr));
}
__device__ __forceinline__ void ldsm_x2(unsigned* r, uint32_t addr) {
    asm volatile("ldmatrix.sync.aligned.m8n8.x2.shared.b16 {%0,%1}, [%2];"
                 : "=r"(r[0]), "=r"(r[1]) : "r"(addr));
}
#define MMA_BF16(acc, ar, br) \
    asm volatile( \
        "mma.sync.aligned.m16n8k16.row.col.f32.bf16.bf16.f32 " \
        "{%0,%1,%2,%3}, {%4,%5,%6,%7}, {%8,%9}, {%0,%1,%2,%3};" \
        : "+f"((acc)[0]), "+f"((acc)[1]), "+f"((acc)[2]), "+f"((acc)[3]) \
        : "r"((ar)[0]), "r"((ar)[1]), "r"((ar)[2]), "r"((ar)[3]), \
          "r"((br)[0]), "r"((br)[1]))

__device__ __forceinline__ u32 key_xform(float sc) {
    u32 u = __float_as_uint(sc);
    return (u & 0x80000000u) ? ~u : (u | 0x80000000u);
}

// ---------------- pipelined bf16 HMMA GEMM with ldmatrix (3-stage) ----------------
static constexpr int ST_ROWB = 80;
static constexpr int ST_HALF = 128 * ST_ROWB;
static constexpr int ST_BYTES = 2 * ST_HALF;
static constexpr int SOFF_STG = 1024;
static constexpr int SMEM_MMA = SOFF_STG + 3 * ST_BYTES;

template <int OUT_BF16, bool BIAS, bool ADD_RES>
__global__ __launch_bounds__(256, 2)
void mma_gemm(const bf16* __restrict__ A, const bf16* __restrict__ B,
              const float* __restrict__ bias, const float* __restrict__ Rres,
              float* __restrict__ Cf, bf16* __restrict__ Ch,
              int N, int Kd, int lda, ll sA, ll sB, ll sC) {
    extern __shared__ char smem[];
    const int tid = threadIdx.x;
    const int warp = tid >> 5, lane = tid & 31;
    const int wm = warp >> 2, wn = warp & 3;
    const int g = lane >> 2, tc = lane & 3;
    const uint32_t sbase = smem_u32(smem);
    const ll z = blockIdx.z;
    const int bm = blockIdx.y * 128, bn = blockIdx.x * 128;
    const bf16* Ag = A + z * sA + (ll)bm * lda;
    const bf16* Bg = B + z * sB + (ll)bn * Kd;

    float* sbias = (float*)smem;
    if (BIAS && tid < 128) sbias[tid] = bias[bn + tid];

    float acc[4][4][4];
    #pragma unroll
    for (int i = 0; i < 4; i++)
        #pragma unroll
        for (int j = 0; j < 4; j++)
            #pragma unroll
            for (int c = 0; c < 4; c++) acc[i][j][c] = 0.f;

    const int nch = Kd >> 5;
    const int lr = tid >> 2;
    const int lc = (tid & 3) << 3;

    const int lrow = lane & 7, lm = lane >> 3;
    uint32_t aoff[4], boff[4];
    #pragma unroll
    for (int mt = 0; mt < 4; mt++)
        aoff[mt] = (uint32_t)((wm * 64 + mt * 16 + (lm & 1) * 8 + lrow) * ST_ROWB
                              + (lm >> 1) * 16);
    #pragma unroll
    for (int nt = 0; nt < 4; nt++)
        boff[nt] = (uint32_t)((wn * 32 + nt * 8 + lrow) * ST_ROWB + (lm & 1) * 16);

    auto load_stage = [&](int i, int s) {
        if (i < nch) {
            const int k0 = i << 5;
            uint32_t sa = sbase + SOFF_STG + s * ST_BYTES;
            uint32_t sb = sa + ST_HALF;
            #pragma unroll
            for (int j = 0; j < 2; j++) {
                int r = lr + j * 64;
                cp_async16(sa + r * ST_ROWB + lc * 2, Ag + (ll)r * lda + k0 + lc);
                cp_async16(sb + r * ST_ROWB + lc * 2, Bg + (ll)r * Kd + k0 + lc);
            }
        }
        cp_commit();
    };

    load_stage(0, 0);
    load_stage(1, 1);

    for (int i = 0; i < nch; i++) {
        cp_wait1();
        __syncthreads();
        load_stage(i + 2, (i + 2) % 3);

        const uint32_t stg = sbase + SOFF_STG + (i % 3) * ST_BYTES;
        #pragma unroll
        for (int ks = 0; ks < 2; ks++) {
            unsigned a_r[4][4], b_r[4][2];
            #pragma unroll
            for (int mt = 0; mt < 4; mt++)
                ldsm_x4(a_r[mt], stg + aoff[mt] + ks * 32);
            #pragma unroll
            for (int nt = 0; nt < 4; nt++)
                ldsm_x2(b_r[nt], stg + ST_HALF + boff[nt] + ks * 32);
            #pragma unroll
            for (int mt = 0; mt < 4; mt++)
                #pragma unroll
                for (int nt = 0; nt < 4; nt++)
                    MMA_BF16(acc[mt][nt], a_r[mt], b_r[nt]);
        }
    }

    #pragma unroll
    for (int mt = 0; mt < 4; mt++) {
        int r0 = bm + wm * 64 + mt * 16 + g;
        #pragma unroll
        for (int nt = 0; nt < 4; nt++) {
            int lcol = wn * 32 + nt * 8 + tc * 2;
            int c0 = bn + lcol;
            #pragma unroll
            for (int h = 0; h < 2; h++) {
                int rr = r0 + h * 8;
                float v0 = acc[mt][nt][h * 2 + 0];
                float v1 = acc[mt][nt][h * 2 + 1];
                if (BIAS) { v0 += sbias[lcol]; v1 += sbias[lcol + 1]; }
                if (ADD_RES) {
                    v0 += Rres[(ll)rr * N + c0];
                    v1 += Rres[(ll)rr * N + c0 + 1];
                }
                if (OUT_BF16) {
                    __nv_bfloat162 pk;
                    pk.x = __float2bfloat16(v0);
                    pk.y = __float2bfloat16(v1);
                    *(__nv_bfloat162*)(Ch + z * sC + (ll)rr * N + c0) = pk;
                } else {
                    *(float2*)(Cf + z * sC + (ll)rr * N + c0) = make_float2(v0, v1);
                }
            }
        }
    }
}

// ---------------- fused g2 GEMM (128x128 tile) + softmax + weighted V ----------------
// CTA: rows [bm, bm+128) of t1 (= 8 points x 16 neighbors), cols [bn, bn+128).
// Softmax over the 16 neighbor rows per point per column is CTA-local.
static constexpr int GA_SOFF = 2048;
static constexpr int GA_SMEM = GA_SOFF + 3 * ST_BYTES;   // 63488
static constexpr int GA_VROWB = 272;                     // V pitch (16B-aligned)

__global__ __launch_bounds__(256, 2)
void g2attn_kernel(const float* __restrict__ g2b) {
    extern __shared__ char smem[];
    const int tid = threadIdx.x;
    const int warp = tid >> 5, lane = tid & 31;
    const int wm = warp >> 2, wn = warp & 3;
    const int g = lane >> 2, tc = lane & 3;
    const uint32_t sbase = smem_u32(smem);
    const int bm = blockIdx.y * 128;          // row block (8 points)
    const int bn = blockIdx.x * 128;          // col block
    const int p0 = bm >> 4;

    float* sb2 = (float*)smem;                // g2_b slice: 128 f32
    int*   snb = (int*)(smem + 1024);         // neighbor ids: 128
    if (tid < 128) {
        sb2[tid] = g2b[bn + tid];
        snb[tid] = g_idx[bm + tid];           // g_idx linear = point*16+k = row
    }

    const bf16* Ag = g_t1 + (ll)bm * CT;
    const bf16* Bg = g_wT[2] + (ll)bn * CT;

    float acc[4][4][4];
    #pragma unroll
    for (int i = 0; i < 4; i++)
        #pragma unroll
        for (int j = 0; j < 4; j++)
            #pragma unroll
            for (int c = 0; c < 4; c++) acc[i][j][c] = 0.f;

    const int lr = tid >> 2;
    const int lc = (tid & 3) << 3;
    const int lrow = lane & 7, lm = lane >> 3;
    uint32_t aoff[4], boff[4];
    #pragma unroll
    for (int mt = 0; mt < 4; mt++)
        aoff[mt] = (uint32_t)((wm * 64 + mt * 16 + (lm & 1) * 8 + lrow) * ST_ROWB
                              + (lm >> 1) * 16);
    #pragma unroll
    for (int nt = 0; nt < 4; nt++)
        boff[nt] = (uint32_t)((wn * 32 + nt * 8 + lrow) * ST_ROWB + (lm & 1) * 16);

    auto load_stage = [&](int i, int s) {
        if (i < 8) {
            const int k0 = i << 5;
            uint32_t sa = sbase + GA_SOFF + s * ST_BYTES;
            uint32_t sb = sa + ST_HALF;
            #pragma unroll
            for (int j = 0; j < 2; j++) {
                int r = lr + j * 64;
                cp_async16(sa + r * ST_ROWB + lc * 2, Ag + (ll)r * CT + k0 + lc);
                cp_async16(sb + r * ST_ROWB + lc * 2, Bg + (ll)r * CT + k0 + lc);
            }
        }
        cp_commit();
    };

    load_stage(0, 0);
    load_stage(1, 1);

    for (int i = 0; i < 8; i++) {
        cp_wait1();
        __syncthreads();
        load_stage(i + 2, (i + 2) % 3);
        const uint32_t stg = sbase + GA_SOFF + (i % 3) * ST_BYTES;
        #pragma unroll
        for (int ks = 0; ks < 2; ks++) {
            unsigned a_r[4][4], b_r[4][2];
            #pragma unroll
            for (int mt = 0; mt < 4; mt++)
                ldsm_x4(a_r[mt], stg + aoff[mt] + ks * 32);
            #pragma unroll
            for (int nt = 0; nt < 4; nt++)
                ldsm_x2(b_r[nt], stg + ST_HALF + boff[nt] + ks * 32);
            #pragma unroll
            for (int mt = 0; mt < 4; mt++)
                #pragma unroll
                for (int nt = 0; nt < 4; nt++)
                    MMA_BF16(acc[mt][nt], a_r[mt], b_r[nt]);
        }
    }
    cp_wait0();
    __syncthreads();   // stage smem dead; sb2/snb ready

    // gather V (bf16): 128 rows x cols [bn, bn+128), pitch 272B
    {
        const int r = tid >> 1, half = tid & 1;
        const int pid = p0 + (r >> 4);
        const int b = pid >> 12;
        const int nbr = snb[r];
        const bf16* vr = g_vh + ((ll)b * CS + nbr) * CT + bn + half * 64;
        char* vrow = smem + GA_SOFF + r * GA_VROWB + half * 128;
        #pragma unroll
        for (int it = 0; it < 8; it++)
            *(uint4*)(vrow + it * 16) = *(const uint4*)(vr + it * 8);
    }
    __syncthreads();

    // softmax over 16 neighbor rows per point per column + weighted V
    const char* sv = smem + GA_SOFF;
    #pragma unroll
    for (int mt = 0; mt < 4; mt++) {
        const int pid = p0 + wm * 4 + mt;
        const int r0 = wm * 64 + mt * 16 + g;
        #pragma unroll
        for (int nt = 0; nt < 4; nt++) {
            const int lcol = wn * 32 + nt * 8 + tc * 2;
            float l00 = (acc[mt][nt][0] + sb2[lcol])     * 0.0625f;
            float l01 = (acc[mt][nt][1] + sb2[lcol + 1]) * 0.0625f;
            float l10 = (acc[mt][nt][2] + sb2[lcol])     * 0.0625f;
            float l11 = (acc[mt][nt][3] + sb2[lcol + 1]) * 0.0625f;
            float m0 = fmaxf(l00, l10), m1 = fmaxf(l01, l11);
            #pragma unroll
            for (int off = 4; off <= 16; off <<= 1) {
                m0 = fmaxf(m0, __shfl_xor_sync(0xFFFFFFFFu, m0, off));
                m1 = fmaxf(m1, __shfl_xor_sync(0xFFFFFFFFu, m1, off));
            }
            float e00 = __expf(l00 - m0), e10 = __expf(l10 - m0);
            float e01 = __expf(l01 - m1), e11 = __expf(l11 - m1);
            float s0 = e00 + e10, s1 = e01 + e11;
            #pragma unroll
            for (int off = 4; off <= 16; off <<= 1) {
                s0 += __shfl_xor_sync(0xFFFFFFFFu, s0, off);
                s1 += __shfl_xor_sync(0xFFFFFFFFu, s1, off);
            }
            __nv_bfloat162 v0 = *(const __nv_bfloat162*)(sv + r0 * GA_VROWB + lcol * 2);
            __nv_bfloat162 v1 = *(const __nv_bfloat162*)(sv + (r0 + 8) * GA_VROWB + lcol * 2);
            float rc0 = e00 * __bfloat162float(v0.x) + e10 * __bfloat162float(v1.x);
            float rc1 = e01 * __bfloat162float(v0.y) + e11 * __bfloat162float(v1.y);
            #pragma unroll
            for (int off = 4; off <= 16; off <<= 1) {
                rc0 += __shfl_xor_sync(0xFFFFFFFFu, rc0, off);
                rc1 += __shfl_xor_sync(0xFFFFFFFFu, rc1, off);
            }
            if (g == 0) {
                __nv_bfloat162 pk;
                pk.x = __float2bfloat16(rc0 / s0);
                pk.y = __float2bfloat16(rc1 / s1);
                *(__nv_bfloat162*)(g_res + (ll)pid * CT + bn + lcol) = pk;
            }
        }
    }
}

// ---------------- symmetric Gram -> packed u32 keys (upper-triangle tiles) ----------------
static constexpr int GS_SOFF = 2048;
static constexpr int GS_TP = 132;                             // u32 pitch (528B)
static constexpr int GS_SMEM = GS_SOFF + 128 * GS_TP * 4;     // 69632

__global__ __launch_bounds__(256, 2)
void gram_sym_kernel() {
    const int bx = blockIdx.x, by = blockIdx.y;
    if (by > bx) return;
    extern __shared__ char smem[];
    const int tid = threadIdx.x;
    const int warp = tid >> 5, lane = tid & 31;
    const int wm = warp >> 2, wn = warp & 3;
    const int g = lane >> 2, tc = lane & 3;
    const uint32_t sbase = smem_u32(smem);
    const ll z = blockIdx.z;
    const int bm = by * 128, bn = bx * 128;
    const bf16* Ag = g_hi + z * CS * CD + (ll)bm * CD;
    const bf16* Bg = g_hi + z * CS * CD + (ll)bn * CD;

    float* ssqr = (float*)smem;
    float* ssqc = (float*)(smem + 512);
    if (tid < 128) {
        ssqr[tid] = g_sq[z * CS + bm + tid];
        ssqc[tid] = g_sq[z * CS + bn + tid];
    }

    float acc[4][4][4];
    #pragma unroll
    for (int i = 0; i < 4; i++)
        #pragma unroll
        for (int j = 0; j < 4; j++)
            #pragma unroll
            for (int c = 0; c < 4; c++) acc[i][j][c] = 0.f;

    const int lr = tid >> 2;
    const int lc = (tid & 3) << 3;
    const int lrow = lane & 7, lm = lane >> 3;
    uint32_t aoff[4], boff[4];
    #pragma unroll
    for (int mt = 0; mt < 4; mt++)
        aoff[mt] = (uint32_t)((wm * 64 + mt * 16 + (lm & 1) * 8 + lrow) * ST_ROWB
                              + (lm >> 1) * 16);
    #pragma unroll
    for (int nt = 0; nt < 4; nt++)
        boff[nt] = (uint32_t)((wn * 32 + nt * 8 + lrow) * ST_ROWB + (lm & 1) * 16);

    auto load_stage = [&](int i, int s) {
        if (i < 8) {
            const int k0 = i << 5;
            uint32_t sa = sbase + GS_SOFF + s * ST_BYTES;
            uint32_t sb = sa + ST_HALF;
            #pragma unroll
            for (int j = 0; j < 2; j++) {
                int r = lr + j * 64;
                cp_async16(sa + r * ST_ROWB + lc * 2, Ag + (ll)r * CD + k0 + lc);
                cp_async16(sb + r * ST_ROWB + lc * 2, Bg + (ll)r * CD + k0 + lc);
            }
        }
        cp_commit();
    };

    load_stage(0, 0);
    load_stage(1, 1);

    for (int i = 0; i < 8; i++) {
        cp_wait1();
        __syncthreads();
        load_stage(i + 2, (i + 2) % 3);
        const uint32_t stg = sbase + GS_SOFF + (i % 3) * ST_BYTES;
        #pragma unroll
        for (int ks = 0; ks < 2; ks++) {
            unsigned a_r[4][4], b_r[4][2];
            #pragma unroll
            for (int mt = 0; mt < 4; mt++)
                ldsm_x4(a_r[mt], stg + aoff[mt] + ks * 32);
            #pragma unroll
            for (int nt = 0; nt < 4; nt++)
                ldsm_x2(b_r[nt], stg + ST_HALF + boff[nt] + ks * 32);
            #pragma unroll
            for (int mt = 0; mt < 4; mt++)
                #pragma unroll
                for (int nt = 0; nt < 4; nt++)
                    MMA_BF16(acc[mt][nt], a_r[mt], b_r[nt]);
        }
    }
    cp_wait0();
    __syncthreads();

    const bool diag = (bx == by);
    u32* st = (u32*)(smem + GS_SOFF);
    u32* Gk = g_gramk + (size_t)z * CS * CS;

    #pragma unroll
    for (int mt = 0; mt < 4; mt++) {
        #pragma unroll
        for (int nt = 0; nt < 4; nt++) {
            int lcol = wn * 32 + nt * 8 + tc * 2;
            #pragma unroll
            for (int h = 0; h < 2; h++) {
                int rl = wm * 64 + mt * 16 + g + h * 8;
                float v0 = acc[mt][nt][h * 2 + 0];
                float v1 = acc[mt][nt][h * 2 + 1];
                u32 kn0 = (key_xform(ssqc[lcol]     - 2.0f * v0) & 0xFFFFF000u) | (u32)(bn + lcol);
                u32 kn1 = (key_xform(ssqc[lcol + 1] - 2.0f * v1) & 0xFFFFF000u) | (u32)(bn + lcol + 1);
                *(uint2*)(Gk + (ll)(bm + rl) * CS + bn + lcol) = make_uint2(kn0, kn1);
                if (!diag) {
                    u32 kt0 = (key_xform(ssqr[rl] - 2.0f * v0) & 0xFFFFF000u) | (u32)(bm + rl);
                    u32 kt1 = (key_xform(ssqr[rl] - 2.0f * v1) & 0xFFFFF000u) | (u32)(bm + rl);
                    st[lcol * GS_TP + rl]       = kt0;
                    st[(lcol + 1) * GS_TP + rl] = kt1;
                }
            }
        }
    }
    if (!diag) {
        __syncthreads();
        const int r = tid >> 1, half = tid & 1;
        u32* dst = Gk + (ll)(bn + r) * CS + bm + half * 64;
        const uint4* src = (const uint4*)(st + r * GS_TP + half * 64);
        #pragma unroll
        for (int q = 0; q < 16; q++)
            ((uint4*)dst)[q] = src[q];
    }
}

// ---------------- pack + sq fused ----------------
__global__ __launch_bounds__(256)
void packsq_kernel(const float* __restrict__ x, float* __restrict__ pos) {
    const int p = blockIdx.x;
    const int t = threadIdx.x;
    const float* xr = x + (ll)p * CIN;
    float v = xr[3 + t];
    g_feat[(ll)p * CD + t] = v;
    g_hi[(ll)p * CD + t] = __float2bfloat16(v);
    if (t < 3) pos[p * 3 + t] = xr[t];
    float s = v * v;
    #pragma unroll
    for (int o = 16; o; o >>= 1) s += __shfl_xor_sync(0xFFFFFFFFu, s, o);
    __shared__ float ws[8];
    if ((t & 31) == 0) ws[t >> 5] = s;
    __syncthreads();
    if (t == 0) {
        float tot = 0.f;
        #pragma unroll
        for (int w = 0; w < 8; w++) tot += ws[w];
        g_sq[p] = tot;
    }
}

__global__ void wqk_prep_kernel(const float* __restrict__ wq, const float* __restrict__ wk,
                                const float* __restrict__ g1) {
    int r = blockIdx.x, c = threadIdx.x;
    float aq = 0.f, ak = 0.f;
    for (int k = 0; k < CT; k++) {
        float gv = g1[k * CT + c];
        aq += wq[r * CT + k] * gv;
        ak += wk[r * CT + k] * gv;
    }
    g_wT[4][c * CT + r] = __float2bfloat16(aq);
    g_wT[5][c * CT + r] = __float2bfloat16(ak);
}

__global__ void tconv4_kernel(const float* __restrict__ fc1, const float* __restrict__ wv,
                              const float* __restrict__ g2, const float* __restrict__ fc2) {
    int n = blockIdx.x, k = threadIdx.x, w = blockIdx.y;
    const float* src = (w == 0) ? fc1 : (w == 1) ? wv : (w == 2) ? g2 : fc2;
    g_wT[w][n * CT + k] = __float2bfloat16(src[k * CT + n]);
}

// ---------------- top-K over pre-packed u32 keys ----------------
__device__ __forceinline__ void ce32(u32& a, u32& b) { if (a > b) { u32 t = a; a = b; b = t; } }
__device__ __forceinline__ void bitonic_sort16(u32* k) {
    #pragma unroll
    for (int sz = 2; sz <= 16; sz <<= 1)
        #pragma unroll
        for (int j = sz >> 1; j > 0; j >>= 1)
            #pragma unroll
            for (int i = 0; i < 16; i++) {
                int l = i ^ j;
                if (l > i) {
                    if ((i & sz) == 0) ce32(k[i], k[l]);
                    else               ce32(k[l], k[i]);
                }
            }
}
__device__ __forceinline__ void bitonic_merge16(u32* k) {
    #pragma unroll
    for (int j = 8; j > 0; j >>= 1)
        #pragma unroll
        for (int i = 0; i < 16; i++)
            if ((i & j) == 0) ce32(k[i], k[i | j]);
}

__global__ __launch_bounds__(256)
void topk_kernel() {
    const int row = blockIdx.x;
    const uint4* __restrict__ G4 = (const uint4*)(g_gramk + (size_t)row * CS);
    const int t = threadIdx.x, lane = t & 31, warp = t >> 5;

    u32 keys[16];
    #pragma unroll
    for (int q = 0; q < 4; q++) {
        uint4 v = G4[q * 256 + t];
        keys[q * 4 + 0] = v.x; keys[q * 4 + 1] = v.y;
        keys[q * 4 + 2] = v.z; keys[q * 4 + 3] = v.w;
    }
    bitonic_sort16(keys);
    #pragma unroll
    for (int d = 1; d < 32; d <<= 1) {
        u32 p[16];
        #pragma unroll
        for (int i = 0; i < 16; i++) p[i] = __shfl_xor_sync(0xFFFFFFFFu, keys[i], d);
        if ((lane & (2 * d - 1)) == 0) {
            #pragma unroll
            for (int i = 0; i < 16; i++) keys[i] = umin(keys[i], p[15 - i]);
            bitonic_merge16(keys);
        }
    }
    __shared__ u32 sk[8][16];
    if (lane == 0)
        #pragma unroll
        for (int i = 0; i < 16; i++) sk[warp][i] = keys[i];
    __syncthreads();
    if (warp == 0) {
        if (lane < 8)
            #pragma unroll
            for (int i = 0; i < 16; i++) keys[i] = sk[lane][i];
        #pragma unroll
        for (int d = 1; d < 8; d <<= 1) {
            u32 p[16];
            #pragma unroll
            for (int i = 0; i < 16; i++) p[i] = __shfl_xor_sync(0xFFFFFFFFu, keys[i], d);
            if (lane < 8 && (lane & (2 * d - 1)) == 0) {
                #pragma unroll
                for (int i = 0; i < 16; i++) keys[i] = umin(keys[i], p[15 - i]);
                bitonic_merge16(keys);
            }
        }
        if (lane == 0)
            #pragma unroll
            for (int i = 0; i < 16; i++) g_idx[row * CK + i] = (int)(keys[i] & 0xFFFu);
    }
}

// ---------------- t1 = relu(qg + g1_b - gather(kg bf16)) -> bf16 ----------------
__global__ __launch_bounds__(256)
void t1_kernel(const float* __restrict__ g1b) {
    const int bn = blockIdx.x;
    const int b = bn >> 12;
    const int t = threadIdx.x;
    __shared__ float qrow[CT];
    __shared__ int nb[CK];
    qrow[t] = g_qg[(ll)bn * CT + t] + g1b[t];
    if (t < CK) nb[t] = g_idx[bn * CK + t];
    __syncthreads();
    #pragma unroll
    for (int k = 0; k < CK; k++) {
        float v = qrow[t] - __bfloat162float(g_kgh[((ll)b * CS + nb[k]) * CT + t]);
        g_t1[((ll)bn * CK + k) * CT + t] = __float2bfloat16(v > 0.f ? v : 0.f);
    }
}

// ---------------- launch ----------------
extern "C" void kernel_launch(void* const* d_in, const int* in_sizes, int n_in,
                              void* d_out, int out_size) {
    const float* x     = (const float*)d_in[0];
    const float* fc1_w = (const float*)d_in[1];
    const float* fc1_b = (const float*)d_in[2];
    const float* fc2_w = (const float*)d_in[3];
    const float* fc2_b = (const float*)d_in[4];
    const float* wq_w  = (const float*)d_in[5];
    const float* wk_w  = (const float*)d_in[6];
    const float* wv_w  = (const float*)d_in[7];
    const float* g1_w  = (const float*)d_in[8];
    const float* g1_b  = (const float*)d_in[9];
    const float* g2_w  = (const float*)d_in[10];
    const float* g2_b  = (const float*)d_in[11];

    float* out     = (float*)d_out;
    float* pos     = out;
    float* outMain = out + CB * CS * 3;

    bf16 *hi, *h, *kgh, *vh, *t1, *res, *wT;
    float *feat, *qg;
    cudaGetSymbolAddress((void**)&hi,   g_hi);
    cudaGetSymbolAddress((void**)&feat, g_feat);
    cudaGetSymbolAddress((void**)&h,    g_h);
    cudaGetSymbolAddress((void**)&qg,   g_qg);
    cudaGetSymbolAddress((void**)&kgh,  g_kgh);
    cudaGetSymbolAddress((void**)&vh,   g_vh);
    cudaGetSymbolAddress((void**)&t1,   g_t1);
    cudaGetSymbolAddress((void**)&res,  g_res);
    cudaGetSymbolAddress((void**)&wT,   g_wT);

    bf16* fc1T = wT + 0 * CT * CT;
    bf16* wvT  = wT + 1 * CT * CT;
    bf16* fc2T = wT + 3 * CT * CT;
    bf16* WqgT = wT + 4 * CT * CT;
    bf16* WkgT = wT + 5 * CT * CT;

    cudaFuncSetAttribute(mma_gemm<0, false, false>, cudaFuncAttributeMaxDynamicSharedMemorySize, SMEM_MMA);
    cudaFuncSetAttribute(mma_gemm<1, false, false>, cudaFuncAttributeMaxDynamicSharedMemorySize, SMEM_MMA);
    cudaFuncSetAttribute(mma_gemm<1, true, false>,  cudaFuncAttributeMaxDynamicSharedMemorySize, SMEM_MMA);
    cudaFuncSetAttribute(mma_gemm<0, true, true>,   cudaFuncAttributeMaxDynamicSharedMemorySize, SMEM_MMA);
    cudaFuncSetAttribute(gram_sym_kernel, cudaFuncAttributeMaxDynamicSharedMemorySize, GS_SMEM);
    cudaFuncSetAttribute(g2attn_kernel, cudaFuncAttributeMaxDynamicSharedMemorySize, GA_SMEM);

    // 1) pack + norms + weight prep
    packsq_kernel<<<CB * CS, 256>>>(x, pos);
    wqk_prep_kernel<<<CT, CT>>>(wq_w, wk_w, g1_w);
    {
        dim3 g(CT, 4, 1);
        tconv4_kernel<<<g, CT>>>(fc1_w, wv_w, g2_w, fc2_w);
    }

    // 2) symmetric Gram -> packed u32 keys
    {
        dim3 g(CS / 128, CS / 128, CB);
        gram_sym_kernel<<<g, 256, GS_SMEM>>>();
    }
    // 3) topk
    topk_kernel<<<CB * CS, 256>>>();

    // 4) h = bf16(feat @ fc1 + b1); qg (f32), kg (bf16), v (bf16)
    {
        dim3 g(CT / 128, (CB * CS) / 128, 1);
        mma_gemm<1, true, false><<<g, 256, SMEM_MMA>>>(
            hi, fc1T, fc1_b, nullptr, nullptr, h, CT, CD, CD, 0, 0, 0);
        mma_gemm<0, false, false><<<g, 256, SMEM_MMA>>>(
            h, WqgT, nullptr, nullptr, qg, nullptr, CT, CT, CT, 0, 0, 0);
        mma_gemm<1, false, false><<<g, 256, SMEM_MMA>>>(
            h, WkgT, nullptr, nullptr, nullptr, kgh, CT, CT, CT, 0, 0, 0);
        mma_gemm<1, false, false><<<g, 256, SMEM_MMA>>>(
            h, wvT, nullptr, nullptr, nullptr, vh, CT, CT, CT, 0, 0, 0);
    }

    // 5) t1 = relu(qg + g1_b - gather(kg))
    t1_kernel<<<CB * CS, 256>>>(g1_b);

    // 6) fused g2 GEMM + softmax + weighted V -> res (128x128 tiles, 2 CTA/SM)
    {
        dim3 g(2, (CB * CS * CK) / 128, 1);
        g2attn_kernel<<<g, 256, GA_SMEM>>>(g2_b);
    }

    // 7) out = res @ fc2 + fc2_b + feat
    {
        dim3 g(CD / 128, (CB * CS) / 128, 1);
        mma_gemm<0, true, true><<<g, 256, SMEM_MMA>>>(
            res, fc2T, fc2_b, feat, outMain, nullptr, CD, CT, CT, 0, 0, 0);
    }
}

// round 17
// speedup vs baseline: 1.5637x; 1.0062x over previous
#include <cuda_runtime.h>
#include <cuda_bf16.h>
#include <cstdint>

#define CB 4
#define CS 4096
#define CD 256
#define CT 256
#define CK 16
#define CIN 259
#define NQKV 768

typedef long long ll;
typedef unsigned u32;
typedef __nv_bfloat16 bf16;

// ---------------- device scratch ----------------
__device__ bf16  g_hi[(size_t)CB * CS * CD];
__device__ float g_feat[CB * CS * CD];
__device__ float g_sq[CB * CS];
__device__ u32   g_gramk[(size_t)CB * CS * CS];        // 256MB packed keys
__device__ int   g_idx[CB * CS * CK];
__device__ bf16  g_h[CB * CS * CT];
__device__ bf16  g_qkv[(size_t)CB * CS * NQKV];        // [qg|kg|v] bf16, 25MB
__device__ bf16  g_t1[(size_t)CB * CS * CK * CT];      // 128MB
__device__ bf16  g_res[CB * CS * CT];
// transposed bf16 weights: 0=fc1, 2=g2, 3=fc2
__device__ bf16  g_wT[4][CT * CT];
__device__ bf16  g_wqkv[NQKV * CT];                    // [WqgT; WkgT; wvT]

// ---------------- helpers ----------------
__device__ __forceinline__ uint32_t smem_u32(const void* p) {
    return (uint32_t)__cvta_generic_to_shared(p);
}
__device__ __forceinline__ void cp_async16(uint32_t s, const void* g) {
    asm volatile("cp.async.cg.shared.global [%0], [%1], 16;" :: "r"(s), "l"(g));
}
__device__ __forceinline__ void cp_commit() {
    asm volatile("cp.async.commit_group;" ::: "memory");
}
__device__ __forceinline__ void cp_wait1() {
    asm volatile("cp.async.wait_group 1;" ::: "memory");
}
__device__ __forceinline__ void cp_wait0() {
    asm volatile("cp.async.wait_group 0;" ::: "memory");
}
__device__ __forceinline__ void ldsm_x4(unsigned* r, uint32_t addr) {
    asm volatile("ldmatrix.sync.aligned.m8n8.x4.shared.b16 {%0,%1,%2,%3}, [%4];"
                 : "=r"(r[0]), "=r"(r[1]), "=r"(r[2]), "=r"(r[3]) : "r"(addr));
}
__device__ __forceinline__ void ldsm_x2(unsigned* r, uint32_t addr) {
    asm volatile("ldmatrix.sync.aligned.m8n8.x2.shared.b16 {%0,%1}, [%2];"
                 : "=r"(r[0]), "=r"(r[1]) : "r"(addr));
}
#define MMA_BF16(acc, ar, br) \
    asm volatile( \
        "mma.sync.aligned.m16n8k16.row.col.f32.bf16.bf16.f32 " \
        "{%0,%1,%2,%3}, {%4,%5,%6,%7}, {%8,%9}, {%0,%1,%2,%3};" \
        : "+f"((acc)[0]), "+f"((acc)[1]), "+f"((acc)[2]), "+f"((acc)[3]) \
        : "r"((ar)[0]), "r"((ar)[1]), "r"((ar)[2]), "r"((ar)[3]), \
          "r"((br)[0]), "r"((br)[1]))

__device__ __forceinline__ u32 key_xform(float sc) {
    u32 u = __float_as_uint(sc);
    return (u & 0x80000000u) ? ~u : (u | 0x80000000u);
}

// ---------------- pipelined bf16 HMMA GEMM with ldmatrix (3-stage) ----------------
static constexpr int ST_ROWB = 80;
static constexpr int ST_HALF = 128 * ST_ROWB;
static constexpr int ST_BYTES = 2 * ST_HALF;
static constexpr int SOFF_STG = 1024;
static constexpr int SMEM_MMA = SOFF_STG + 3 * ST_BYTES;

template <int OUT_BF16, bool BIAS, bool ADD_RES>
__global__ __launch_bounds__(256, 2)
void mma_gemm(const bf16* __restrict__ A, const bf16* __restrict__ B,
              const float* __restrict__ bias, const float* __restrict__ Rres,
              float* __restrict__ Cf, bf16* __restrict__ Ch,
              int N, int Kd, int lda, ll sA, ll sB, ll sC) {
    extern __shared__ char smem[];
    const int tid = threadIdx.x;
    const int warp = tid >> 5, lane = tid & 31;
    const int wm = warp >> 2, wn = warp & 3;
    const int g = lane >> 2, tc = lane & 3;
    const uint32_t sbase = smem_u32(smem);
    const ll z = blockIdx.z;
    const int bm = blockIdx.y * 128, bn = blockIdx.x * 128;
    const bf16* Ag = A + z * sA + (ll)bm * lda;
    const bf16* Bg = B + z * sB + (ll)bn * Kd;

    float* sbias = (float*)smem;
    if (BIAS && tid < 128) sbias[tid] = bias[bn + tid];

    float acc[4][4][4];
    #pragma unroll
    for (int i = 0; i < 4; i++)
        #pragma unroll
        for (int j = 0; j < 4; j++)
            #pragma unroll
            for (int c = 0; c < 4; c++) acc[i][j][c] = 0.f;

    const int nch = Kd >> 5;
    const int lr = tid >> 2;
    const int lc = (tid & 3) << 3;

    const int lrow = lane & 7, lm = lane >> 3;
    uint32_t aoff[4], boff[4];
    #pragma unroll
    for (int mt = 0; mt < 4; mt++)
        aoff[mt] = (uint32_t)((wm * 64 + mt * 16 + (lm & 1) * 8 + lrow) * ST_ROWB
                              + (lm >> 1) * 16);
    #pragma unroll
    for (int nt = 0; nt < 4; nt++)
        boff[nt] = (uint32_t)((wn * 32 + nt * 8 + lrow) * ST_ROWB + (lm & 1) * 16);

    auto load_stage = [&](int i, int s) {
        if (i < nch) {
            const int k0 = i << 5;
            uint32_t sa = sbase + SOFF_STG + s * ST_BYTES;
            uint32_t sb = sa + ST_HALF;
            #pragma unroll
            for (int j = 0; j < 2; j++) {
                int r = lr + j * 64;
                cp_async16(sa + r * ST_ROWB + lc * 2, Ag + (ll)r * lda + k0 + lc);
                cp_async16(sb + r * ST_ROWB + lc * 2, Bg + (ll)r * Kd + k0 + lc);
            }
        }
        cp_commit();
    };

    load_stage(0, 0);
    load_stage(1, 1);

    for (int i = 0; i < nch; i++) {
        cp_wait1();
        __syncthreads();
        load_stage(i + 2, (i + 2) % 3);

        const uint32_t stg = sbase + SOFF_STG + (i % 3) * ST_BYTES;
        #pragma unroll
        for (int ks = 0; ks < 2; ks++) {
            unsigned a_r[4][4], b_r[4][2];
            #pragma unroll
            for (int mt = 0; mt < 4; mt++)
                ldsm_x4(a_r[mt], stg + aoff[mt] + ks * 32);
            #pragma unroll
            for (int nt = 0; nt < 4; nt++)
                ldsm_x2(b_r[nt], stg + ST_HALF + boff[nt] + ks * 32);
            #pragma unroll
            for (int mt = 0; mt < 4; mt++)
                #pragma unroll
                for (int nt = 0; nt < 4; nt++)
                    MMA_BF16(acc[mt][nt], a_r[mt], b_r[nt]);
        }
    }

    #pragma unroll
    for (int mt = 0; mt < 4; mt++) {
        int r0 = bm + wm * 64 + mt * 16 + g;
        #pragma unroll
        for (int nt = 0; nt < 4; nt++) {
            int lcol = wn * 32 + nt * 8 + tc * 2;
            int c0 = bn + lcol;
            #pragma unroll
            for (int h = 0; h < 2; h++) {
                int rr = r0 + h * 8;
                float v0 = acc[mt][nt][h * 2 + 0];
                float v1 = acc[mt][nt][h * 2 + 1];
                if (BIAS) { v0 += sbias[lcol]; v1 += sbias[lcol + 1]; }
                if (ADD_RES) {
                    v0 += Rres[(ll)rr * N + c0];
                    v1 += Rres[(ll)rr * N + c0 + 1];
                }
                if (OUT_BF16) {
                    __nv_bfloat162 pk;
                    pk.x = __float2bfloat16(v0);
                    pk.y = __float2bfloat16(v1);
                    *(__nv_bfloat162*)(Ch + z * sC + (ll)rr * N + c0) = pk;
                } else {
                    *(float2*)(Cf + z * sC + (ll)rr * N + c0) = make_float2(v0, v1);
                }
            }
        }
    }
}

// ---------------- fused g2 GEMM (128x128 tile) + softmax + weighted V ----------------
static constexpr int GA_SOFF = 2048;
static constexpr int GA_SMEM = GA_SOFF + 3 * ST_BYTES;   // 63488
static constexpr int GA_VROWB = 272;                     // V pitch (16B-aligned)

__global__ __launch_bounds__(256, 2)
void g2attn_kernel(const float* __restrict__ g2b) {
    extern __shared__ char smem[];
    const int tid = threadIdx.x;
    const int warp = tid >> 5, lane = tid & 31;
    const int wm = warp >> 2, wn = warp & 3;
    const int g = lane >> 2, tc = lane & 3;
    const uint32_t sbase = smem_u32(smem);
    const int bm = blockIdx.y * 128;          // row block (8 points)
    const int bn = blockIdx.x * 128;          // col block
    const int p0 = bm >> 4;

    float* sb2 = (float*)smem;
    int*   snb = (int*)(smem + 1024);
    if (tid < 128) {
        sb2[tid] = g2b[bn + tid];
        snb[tid] = g_idx[bm + tid];
    }

    const bf16* Ag = g_t1 + (ll)bm * CT;
    const bf16* Bg = g_wT[2] + (ll)bn * CT;

    float acc[4][4][4];
    #pragma unroll
    for (int i = 0; i < 4; i++)
        #pragma unroll
        for (int j = 0; j < 4; j++)
            #pragma unroll
            for (int c = 0; c < 4; c++) acc[i][j][c] = 0.f;

    const int lr = tid >> 2;
    const int lc = (tid & 3) << 3;
    const int lrow = lane & 7, lm = lane >> 3;
    uint32_t aoff[4], boff[4];
    #pragma unroll
    for (int mt = 0; mt < 4; mt++)
        aoff[mt] = (uint32_t)((wm * 64 + mt * 16 + (lm & 1) * 8 + lrow) * ST_ROWB
                              + (lm >> 1) * 16);
    #pragma unroll
    for (int nt = 0; nt < 4; nt++)
        boff[nt] = (uint32_t)((wn * 32 + nt * 8 + lrow) * ST_ROWB + (lm & 1) * 16);

    auto load_stage = [&](int i, int s) {
        if (i < 8) {
            const int k0 = i << 5;
            uint32_t sa = sbase + GA_SOFF + s * ST_BYTES;
            uint32_t sb = sa + ST_HALF;
            #pragma unroll
            for (int j = 0; j < 2; j++) {
                int r = lr + j * 64;
                cp_async16(sa + r * ST_ROWB + lc * 2, Ag + (ll)r * CT + k0 + lc);
                cp_async16(sb + r * ST_ROWB + lc * 2, Bg + (ll)r * CT + k0 + lc);
            }
        }
        cp_commit();
    };

    load_stage(0, 0);
    load_stage(1, 1);

    for (int i = 0; i < 8; i++) {
        cp_wait1();
        __syncthreads();
        load_stage(i + 2, (i + 2) % 3);
        const uint32_t stg = sbase + GA_SOFF + (i % 3) * ST_BYTES;
        #pragma unroll
        for (int ks = 0; ks < 2; ks++) {
            unsigned a_r[4][4], b_r[4][2];
            #pragma unroll
            for (int mt = 0; mt < 4; mt++)
                ldsm_x4(a_r[mt], stg + aoff[mt] + ks * 32);
            #pragma unroll
            for (int nt = 0; nt < 4; nt++)
                ldsm_x2(b_r[nt], stg + ST_HALF + boff[nt] + ks * 32);
            #pragma unroll
            for (int mt = 0; mt < 4; mt++)
                #pragma unroll
                for (int nt = 0; nt < 4; nt++)
                    MMA_BF16(acc[mt][nt], a_r[mt], b_r[nt]);
        }
    }
    cp_wait0();
    __syncthreads();

    // gather V (bf16) from qkv block 2: 128 rows x cols [bn, bn+128)
    {
        const int r = tid >> 1, half = tid & 1;
        const int pid = p0 + (r >> 4);
        const int b = pid >> 12;
        const int nbr = snb[r];
        const bf16* vr = g_qkv + ((ll)b * CS + nbr) * NQKV + 512 + bn + half * 64;
        char* vrow = smem + GA_SOFF + r * GA_VROWB + half * 128;
        #pragma unroll
        for (int it = 0; it < 8; it++)
            *(uint4*)(vrow + it * 16) = *(const uint4*)(vr + it * 8);
    }
    __syncthreads();

    const char* sv = smem + GA_SOFF;
    #pragma unroll
    for (int mt = 0; mt < 4; mt++) {
        const int pid = p0 + wm * 4 + mt;
        const int r0 = wm * 64 + mt * 16 + g;
        #pragma unroll
        for (int nt = 0; nt < 4; nt++) {
            const int lcol = wn * 32 + nt * 8 + tc * 2;
            float l00 = (acc[mt][nt][0] + sb2[lcol])     * 0.0625f;
            float l01 = (acc[mt][nt][1] + sb2[lcol + 1]) * 0.0625f;
            float l10 = (acc[mt][nt][2] + sb2[lcol])     * 0.0625f;
            float l11 = (acc[mt][nt][3] + sb2[lcol + 1]) * 0.0625f;
            float m0 = fmaxf(l00, l10), m1 = fmaxf(l01, l11);
            #pragma unroll
            for (int off = 4; off <= 16; off <<= 1) {
                m0 = fmaxf(m0, __shfl_xor_sync(0xFFFFFFFFu, m0, off));
                m1 = fmaxf(m1, __shfl_xor_sync(0xFFFFFFFFu, m1, off));
            }
            float e00 = __expf(l00 - m0), e10 = __expf(l10 - m0);
            float e01 = __expf(l01 - m1), e11 = __expf(l11 - m1);
            float s0 = e00 + e10, s1 = e01 + e11;
            #pragma unroll
            for (int off = 4; off <= 16; off <<= 1) {
                s0 += __shfl_xor_sync(0xFFFFFFFFu, s0, off);
                s1 += __shfl_xor_sync(0xFFFFFFFFu, s1, off);
            }
            __nv_bfloat162 v0 = *(const __nv_bfloat162*)(sv + r0 * GA_VROWB + lcol * 2);
            __nv_bfloat162 v1 = *(const __nv_bfloat162*)(sv + (r0 + 8) * GA_VROWB + lcol * 2);
            float rc0 = e00 * __bfloat162float(v0.x) + e10 * __bfloat162float(v1.x);
            float rc1 = e01 * __bfloat162float(v0.y) + e11 * __bfloat162float(v1.y);
            #pragma unroll
            for (int off = 4; off <= 16; off <<= 1) {
                rc0 += __shfl_xor_sync(0xFFFFFFFFu, rc0, off);
                rc1 += __shfl_xor_sync(0xFFFFFFFFu, rc1, off);
            }
            if (g == 0) {
                __nv_bfloat162 pk;
                pk.x = __float2bfloat16(rc0 / s0);
                pk.y = __float2bfloat16(rc1 / s1);
                *(__nv_bfloat162*)(g_res + (ll)pid * CT + bn + lcol) = pk;
            }
        }
    }
}

// ---------------- symmetric Gram -> packed u32 keys (upper-triangle tiles) ----------------
static constexpr int GS_SOFF = 2048;
static constexpr int GS_TP = 132;
static constexpr int GS_SMEM = GS_SOFF + 128 * GS_TP * 4;

__global__ __launch_bounds__(256, 2)
void gram_sym_kernel() {
    const int bx = blockIdx.x, by = blockIdx.y;
    if (by > bx) return;
    extern __shared__ char smem[];
    const int tid = threadIdx.x;
    const int warp = tid >> 5, lane = tid & 31;
    const int wm = warp >> 2, wn = warp & 3;
    const int g = lane >> 2, tc = lane & 3;
    const uint32_t sbase = smem_u32(smem);
    const ll z = blockIdx.z;
    const int bm = by * 128, bn = bx * 128;
    const bf16* Ag = g_hi + z * CS * CD + (ll)bm * CD;
    const bf16* Bg = g_hi + z * CS * CD + (ll)bn * CD;

    float* ssqr = (float*)smem;
    float* ssqc = (float*)(smem + 512);
    if (tid < 128) {
        ssqr[tid] = g_sq[z * CS + bm + tid];
        ssqc[tid] = g_sq[z * CS + bn + tid];
    }

    float acc[4][4][4];
    #pragma unroll
    for (int i = 0; i < 4; i++)
        #pragma unroll
        for (int j = 0; j < 4; j++)
            #pragma unroll
            for (int c = 0; c < 4; c++) acc[i][j][c] = 0.f;

    const int lr = tid >> 2;
    const int lc = (tid & 3) << 3;
    const int lrow = lane & 7, lm = lane >> 3;
    uint32_t aoff[4], boff[4];
    #pragma unroll
    for (int mt = 0; mt < 4; mt++)
        aoff[mt] = (uint32_t)((wm * 64 + mt * 16 + (lm & 1) * 8 + lrow) * ST_ROWB
                              + (lm >> 1) * 16);
    #pragma unroll
    for (int nt = 0; nt < 4; nt++)
        boff[nt] = (uint32_t)((wn * 32 + nt * 8 + lrow) * ST_ROWB + (lm & 1) * 16);

    auto load_stage = [&](int i, int s) {
        if (i < 8) {
            const int k0 = i << 5;
            uint32_t sa = sbase + GS_SOFF + s * ST_BYTES;
            uint32_t sb = sa + ST_HALF;
            #pragma unroll
            for (int j = 0; j < 2; j++) {
                int r = lr + j * 64;
                cp_async16(sa + r * ST_ROWB + lc * 2, Ag + (ll)r * CD + k0 + lc);
                cp_async16(sb + r * ST_ROWB + lc * 2, Bg + (ll)r * CD + k0 + lc);
            }
        }
        cp_commit();
    };

    load_stage(0, 0);
    load_stage(1, 1);

    for (int i = 0; i < 8; i++) {
        cp_wait1();
        __syncthreads();
        load_stage(i + 2, (i + 2) % 3);
        const uint32_t stg = sbase + GS_SOFF + (i % 3) * ST_BYTES;
        #pragma unroll
        for (int ks = 0; ks < 2; ks++) {
            unsigned a_r[4][4], b_r[4][2];
            #pragma unroll
            for (int mt = 0; mt < 4; mt++)
                ldsm_x4(a_r[mt], stg + aoff[mt] + ks * 32);
            #pragma unroll
            for (int nt = 0; nt < 4; nt++)
                ldsm_x2(b_r[nt], stg + ST_HALF + boff[nt] + ks * 32);
            #pragma unroll
            for (int mt = 0; mt < 4; mt++)
                #pragma unroll
                for (int nt = 0; nt < 4; nt++)
                    MMA_BF16(acc[mt][nt], a_r[mt], b_r[nt]);
        }
    }
    cp_wait0();
    __syncthreads();

    const bool diag = (bx == by);
    u32* st = (u32*)(smem + GS_SOFF);
    u32* Gk = g_gramk + (size_t)z * CS * CS;

    #pragma unroll
    for (int mt = 0; mt < 4; mt++) {
        #pragma unroll
        for (int nt = 0; nt < 4; nt++) {
            int lcol = wn * 32 + nt * 8 + tc * 2;
            #pragma unroll
            for (int h = 0; h < 2; h++) {
                int rl = wm * 64 + mt * 16 + g + h * 8;
                float v0 = acc[mt][nt][h * 2 + 0];
                float v1 = acc[mt][nt][h * 2 + 1];
                u32 kn0 = (key_xform(ssqc[lcol]     - 2.0f * v0) & 0xFFFFF000u) | (u32)(bn + lcol);
                u32 kn1 = (key_xform(ssqc[lcol + 1] - 2.0f * v1) & 0xFFFFF000u) | (u32)(bn + lcol + 1);
                *(uint2*)(Gk + (ll)(bm + rl) * CS + bn + lcol) = make_uint2(kn0, kn1);
                if (!diag) {
                    u32 kt0 = (key_xform(ssqr[rl] - 2.0f * v0) & 0xFFFFF000u) | (u32)(bm + rl);
                    u32 kt1 = (key_xform(ssqr[rl] - 2.0f * v1) & 0xFFFFF000u) | (u32)(bm + rl);
                    st[lcol * GS_TP + rl]       = kt0;
                    st[(lcol + 1) * GS_TP + rl] = kt1;
                }
            }
        }
    }
    if (!diag) {
        __syncthreads();
        const int r = tid >> 1, half = tid & 1;
        u32* dst = Gk + (ll)(bn + r) * CS + bm + half * 64;
        const uint4* src = (const uint4*)(st + r * GS_TP + half * 64);
        #pragma unroll
        for (int q = 0; q < 16; q++)
            ((uint4*)dst)[q] = src[q];
    }
}

// ---------------- pack + sq fused ----------------
__global__ __launch_bounds__(256)
void packsq_kernel(const float* __restrict__ x, float* __restrict__ pos) {
    const int p = blockIdx.x;
    const int t = threadIdx.x;
    const float* xr = x + (ll)p * CIN;
    float v = xr[3 + t];
    g_feat[(ll)p * CD + t] = v;
    g_hi[(ll)p * CD + t] = __float2bfloat16(v);
    if (t < 3) pos[p * 3 + t] = xr[t];
    float s = v * v;
    #pragma unroll
    for (int o = 16; o; o >>= 1) s += __shfl_xor_sync(0xFFFFFFFFu, s, o);
    __shared__ float ws[8];
    if ((t & 31) == 0) ws[t >> 5] = s;
    __syncthreads();
    if (t == 0) {
        float tot = 0.f;
        #pragma unroll
        for (int w = 0; w < 8; w++) tot += ws[w];
        g_sq[p] = tot;
    }
}

// Wqg = wq@g1, Wkg = wk@g1 -> rows 0..255 / 256..511 of g_wqkv (transposed)
__global__ void wqk_prep_kernel(const float* __restrict__ wq, const float* __restrict__ wk,
                                const float* __restrict__ g1) {
    int r = blockIdx.x, c = threadIdx.x;
    float aq = 0.f, ak = 0.f;
    for (int k = 0; k < CT; k++) {
        float gv = g1[k * CT + c];
        aq += wq[r * CT + k] * gv;
        ak += wk[r * CT + k] * gv;
    }
    g_wqkv[c * CT + r]            = __float2bfloat16(aq);
    g_wqkv[(CT + c) * CT + r]     = __float2bfloat16(ak);
}

__global__ void tconv4_kernel(const float* __restrict__ fc1, const float* __restrict__ wv,
                              const float* __restrict__ g2, const float* __restrict__ fc2) {
    int n = blockIdx.x, k = threadIdx.x, w = blockIdx.y;
    if (w == 1) {
        g_wqkv[(2 * CT + n) * CT + k] = __float2bfloat16(wv[k * CT + n]);
    } else {
        const float* src = (w == 0) ? fc1 : (w == 2) ? g2 : fc2;
        g_wT[w][n * CT + k] = __float2bfloat16(src[k * CT + n]);
    }
}

// ---------------- top-K over pre-packed u32 keys ----------------
__device__ __forceinline__ void ce32(u32& a, u32& b) { if (a > b) { u32 t = a; a = b; b = t; } }
__device__ __forceinline__ void bitonic_sort16(u32* k) {
    #pragma unroll
    for (int sz = 2; sz <= 16; sz <<= 1)
        #pragma unroll
        for (int j = sz >> 1; j > 0; j >>= 1)
            #pragma unroll
            for (int i = 0; i < 16; i++) {
                int l = i ^ j;
                if (l > i) {
                    if ((i & sz) == 0) ce32(k[i], k[l]);
                    else               ce32(k[l], k[i]);
                }
            }
}
__device__ __forceinline__ void bitonic_merge16(u32* k) {
    #pragma unroll
    for (int j = 8; j > 0; j >>= 1)
        #pragma unroll
        for (int i = 0; i < 16; i++)
            if ((i & j) == 0) ce32(k[i], k[i | j]);
}

__global__ __launch_bounds__(256)
void topk_kernel() {
    const int row = blockIdx.x;
    const uint4* __restrict__ G4 = (const uint4*)(g_gramk + (size_t)row * CS);
    const int t = threadIdx.x, lane = t & 31, warp = t >> 5;

    u32 keys[16];
    #pragma unroll
    for (int q = 0; q < 4; q++) {
        uint4 v = G4[q * 256 + t];
        keys[q * 4 + 0] = v.x; keys[q * 4 + 1] = v.y;
        keys[q * 4 + 2] = v.z; keys[q * 4 + 3] = v.w;
    }
    bitonic_sort16(keys);
    #pragma unroll
    for (int d = 1; d < 32; d <<= 1) {
        u32 p[16];
        #pragma unroll
        for (int i = 0; i < 16; i++) p[i] = __shfl_xor_sync(0xFFFFFFFFu, keys[i], d);
        if ((lane & (2 * d - 1)) == 0) {
            #pragma unroll
            for (int i = 0; i < 16; i++) keys[i] = umin(keys[i], p[15 - i]);
            bitonic_merge16(keys);
        }
    }
    __shared__ u32 sk[8][16];
    if (lane == 0)
        #pragma unroll
        for (int i = 0; i < 16; i++) sk[warp][i] = keys[i];
    __syncthreads();
    if (warp == 0) {
        if (lane < 8)
            #pragma unroll
            for (int i = 0; i < 16; i++) keys[i] = sk[lane][i];
        #pragma unroll
        for (int d = 1; d < 8; d <<= 1) {
            u32 p[16];
            #pragma unroll
            for (int i = 0; i < 16; i++) p[i] = __shfl_xor_sync(0xFFFFFFFFu, keys[i], d);
            if (lane < 8 && (lane & (2 * d - 1)) == 0) {
                #pragma unroll
                for (int i = 0; i < 16; i++) keys[i] = umin(keys[i], p[15 - i]);
                bitonic_merge16(keys);
            }
        }
        if (lane == 0)
            #pragma unroll
            for (int i = 0; i < 16; i++) g_idx[row * CK + i] = (int)(keys[i] & 0xFFFu);
    }
}

// ---------------- t1 = relu(qg + g1_b - gather(kg)) -> bf16 (qkv layout) ----------------
__global__ __launch_bounds__(256)
void t1_kernel(const float* __restrict__ g1b) {
    const int bn = blockIdx.x;
    const int b = bn >> 12;
    const int t = threadIdx.x;
    __shared__ float qrow[CT];
    __shared__ int nb[CK];
    qrow[t] = __bfloat162float(g_qkv[(ll)bn * NQKV + t]) + g1b[t];
    if (t < CK) nb[t] = g_idx[bn * CK + t];
    __syncthreads();
    #pragma unroll
    for (int k = 0; k < CK; k++) {
        float v = qrow[t] - __bfloat162float(g_qkv[((ll)b * CS + nb[k]) * NQKV + CT + t]);
        g_t1[((ll)bn * CK + k) * CT + t] = __float2bfloat16(v > 0.f ? v : 0.f);
    }
}

// ---------------- launch ----------------
extern "C" void kernel_launch(void* const* d_in, const int* in_sizes, int n_in,
                              void* d_out, int out_size) {
    const float* x     = (const float*)d_in[0];
    const float* fc1_w = (const float*)d_in[1];
    const float* fc1_b = (const float*)d_in[2];
    const float* fc2_w = (const float*)d_in[3];
    const float* fc2_b = (const float*)d_in[4];
    const float* wq_w  = (const float*)d_in[5];
    const float* wk_w  = (const float*)d_in[6];
    const float* wv_w  = (const float*)d_in[7];
    const float* g1_w  = (const float*)d_in[8];
    const float* g1_b  = (const float*)d_in[9];
    const float* g2_w  = (const float*)d_in[10];
    const float* g2_b  = (const float*)d_in[11];

    float* out     = (float*)d_out;
    float* pos     = out;
    float* outMain = out + CB * CS * 3;

    bf16 *hi, *h, *qkv, *t1, *res, *wT, *wqkv;
    float *feat;
    cudaGetSymbolAddress((void**)&hi,   g_hi);
    cudaGetSymbolAddress((void**)&feat, g_feat);
    cudaGetSymbolAddress((void**)&h,    g_h);
    cudaGetSymbolAddress((void**)&qkv,  g_qkv);
    cudaGetSymbolAddress((void**)&t1,   g_t1);
    cudaGetSymbolAddress((void**)&res,  g_res);
    cudaGetSymbolAddress((void**)&wT,   g_wT);
    cudaGetSymbolAddress((void**)&wqkv, g_wqkv);

    bf16* fc1T = wT + 0 * CT * CT;
    bf16* fc2T = wT + 3 * CT * CT;

    cudaFuncSetAttribute(mma_gemm<1, false, false>, cudaFuncAttributeMaxDynamicSharedMemorySize, SMEM_MMA);
    cudaFuncSetAttribute(mma_gemm<1, true, false>,  cudaFuncAttributeMaxDynamicSharedMemorySize, SMEM_MMA);
    cudaFuncSetAttribute(mma_gemm<0, true, true>,   cudaFuncAttributeMaxDynamicSharedMemorySize, SMEM_MMA);
    cudaFuncSetAttribute(gram_sym_kernel, cudaFuncAttributeMaxDynamicSharedMemorySize, GS_SMEM);
    cudaFuncSetAttribute(g2attn_kernel, cudaFuncAttributeMaxDynamicSharedMemorySize, GA_SMEM);

    // 1) pack + norms + weight prep
    packsq_kernel<<<CB * CS, 256>>>(x, pos);
    wqk_prep_kernel<<<CT, CT>>>(wq_w, wk_w, g1_w);
    {
        dim3 g(CT, 4, 1);
        tconv4_kernel<<<g, CT>>>(fc1_w, wv_w, g2_w, fc2_w);
    }

    // 2) symmetric Gram -> packed u32 keys
    {
        dim3 g(CS / 128, CS / 128, CB);
        gram_sym_kernel<<<g, 256, GS_SMEM>>>();
    }
    // 3) topk
    topk_kernel<<<CB * CS, 256>>>();

    // 4) h = bf16(feat @ fc1 + b1); qkv = h @ [Wqg|Wkg|wv] (one N=768 GEMM, bf16)
    {
        dim3 g(CT / 128, (CB * CS) / 128, 1);
        mma_gemm<1, true, false><<<g, 256, SMEM_MMA>>>(
            hi, fc1T, fc1_b, nullptr, nullptr, h, CT, CD, CD, 0, 0, 0);
    }
    {
        dim3 g(NQKV / 128, (CB * CS) / 128, 1);
        mma_gemm<1, false, false><<<g, 256, SMEM_MMA>>>(
            h, wqkv, nullptr, nullptr, nullptr, qkv, NQKV, CT, CT, 0, 0, 0);
    }

    // 5) t1 = relu(qg + g1_b - gather(kg))
    t1_kernel<<<CB * CS, 256>>>(g1_b);

    // 6) fused g2 GEMM + softmax + weighted V -> res
    {
        dim3 g(2, (CB * CS * CK) / 128, 1);
        g2attn_kernel<<<g, 256, GA_SMEM>>>(g2_b);
    }

    // 7) out = res @ fc2 + fc2_b + feat
    {
        dim3 g(CD / 128, (CB * CS) / 128, 1);
        mma_gemm<0, true, true><<<g, 256, SMEM_MMA>>>(
            res, fc2T, fc2_b, feat, outMain, nullptr, CD, CT, CT, 0, 0, 0);
    }
}